// round 1
// baseline (speedup 1.0000x reference)
#include <cuda_runtime.h>
#include <math.h>

#define EPSV 1e-5f

constexpr int C   = 128;
constexpr int CH  = 256;   // C*H
constexpr int KK  = 27;
constexpr int MM  = 2;
constexpr int NPTS = 131072;
constexpr int NSB = 512;   // stat partial blocks

// ---------------- device scratch (static; no allocations allowed) --------------
__device__ float g_v   [(size_t)NPTS * CH];   // x @ Wv (pre-BN)
__device__ float g_P   [(size_t)NPTS * KK];   // x @ Wq^T
__device__ float g_q   [NPTS];                // raw q (pre-BN)
__device__ float g_out1[(size_t)NPTS * CH];   // routed gather output
__device__ float g_y   [(size_t)NPTS * C];    // out1 @ Wout (pre-BN)
__device__ float g_part[NSB * 512];           // generic column-stat partials
__device__ float g_qpart[2 * NSB];            // q stat partials
__device__ float g_vab [2 * CH];              // v BN affine (a, b)
__device__ float g_qab [2];                   // q BN affine
__device__ float g_yab [2 * C];               // y BN affine
__device__ float g_ksum[MM * KK];             // cb.sum(-1)
__device__ float g_choice[(size_t)NPTS * MM];

// ---------------- SGEMM: A[N,Kd] @ B[Kd,Ncols], 128x128 block, 8x8 microtile ---
template<int Kd>
__global__ void __launch_bounds__(256) sgemm_kernel(
    const float* __restrict__ A, const float* __restrict__ B,
    float* __restrict__ Cm, int Ncols)
{
    constexpr int BM = 128, BN = 128, BK = 16;
    __shared__ float As[BM][BK + 1];
    __shared__ float Bs[BK][BN];
    const int tid = threadIdx.x;
    const int tx = tid & 15, ty = tid >> 4;
    const int rowBase = blockIdx.x * BM;
    const int colBase = blockIdx.y * BN;

    float acc[8][8];
#pragma unroll
    for (int i = 0; i < 8; i++)
#pragma unroll
        for (int j = 0; j < 8; j++) acc[i][j] = 0.f;

    for (int k0 = 0; k0 < Kd; k0 += BK) {
#pragma unroll
        for (int it = 0; it < 2; it++) {
            int idx = it * 256 + tid;          // 0..511 float4 slots
            int r  = idx >> 2;                 // 0..127
            int kq = (idx & 3) << 2;           // 0,4,8,12
            float4 av = *reinterpret_cast<const float4*>(
                &A[(size_t)(rowBase + r) * Kd + k0 + kq]);
            As[r][kq + 0] = av.x; As[r][kq + 1] = av.y;
            As[r][kq + 2] = av.z; As[r][kq + 3] = av.w;
            int bk = idx >> 5;                 // 0..15
            int bc = (idx & 31) << 2;          // 0..124
            *reinterpret_cast<float4*>(&Bs[bk][bc]) =
                *reinterpret_cast<const float4*>(
                    &B[(size_t)(k0 + bk) * Ncols + colBase + bc]);
        }
        __syncthreads();
#pragma unroll
        for (int k = 0; k < BK; k++) {
            float ra[8], rb[8];
#pragma unroll
            for (int i = 0; i < 8; i++) ra[i] = As[ty * 8 + i][k];
            float4 b0 = *reinterpret_cast<const float4*>(&Bs[k][tx * 8]);
            float4 b1 = *reinterpret_cast<const float4*>(&Bs[k][tx * 8 + 4]);
            rb[0] = b0.x; rb[1] = b0.y; rb[2] = b0.z; rb[3] = b0.w;
            rb[4] = b1.x; rb[5] = b1.y; rb[6] = b1.z; rb[7] = b1.w;
#pragma unroll
            for (int i = 0; i < 8; i++)
#pragma unroll
                for (int j = 0; j < 8; j++)
                    acc[i][j] = fmaf(ra[i], rb[j], acc[i][j]);
        }
        __syncthreads();
    }
#pragma unroll
    for (int i = 0; i < 8; i++) {
        size_t r = (size_t)rowBase + ty * 8 + i;
        float4* o = reinterpret_cast<float4*>(&Cm[r * Ncols + colBase + tx * 8]);
        o[0] = make_float4(acc[i][0], acc[i][1], acc[i][2], acc[i][3]);
        o[1] = make_float4(acc[i][4], acc[i][5], acc[i][6], acc[i][7]);
    }
}

// ---------------- P = x @ Wq^T : one warp per row, Wq [27,128] in shared -------
__global__ void __launch_bounds__(256) p_gemm(
    const float* __restrict__ x, const float* __restrict__ Wq,
    float* __restrict__ P)
{
    __shared__ float wqs[KK * C];
    for (int i = threadIdx.x; i < KK * C; i += 256) wqs[i] = Wq[i];
    __syncthreads();
    const int warp = threadIdx.x >> 5, lane = threadIdx.x & 31;
    const int row = blockIdx.x * 8 + warp;
    float4 xv = reinterpret_cast<const float4*>(x + (size_t)row * C)[lane];
#pragma unroll
    for (int k = 0; k < KK; k++) {
        float4 w = reinterpret_cast<const float4*>(wqs + k * C)[lane];
        float d = xv.x * w.x + xv.y * w.y + xv.z * w.z + xv.w * w.w;
#pragma unroll
        for (int o = 16; o; o >>= 1) d += __shfl_xor_sync(0xFFFFFFFFu, d, o);
        if (lane == 0) P[(size_t)row * KK + k] = d;
    }
}

// ---------------- column stats: deterministic two-pass (no atomics) ------------
__global__ void colstats_kernel(const float* __restrict__ data, size_t perBlock,
                                float* __restrict__ part)
{
    size_t base = perBlock * blockIdx.x;
    float s = 0.f, s2 = 0.f;
    for (size_t i = base + threadIdx.x; i < base + perBlock; i += 256) {
        float v = data[i];
        s += v; s2 = fmaf(v, v, s2);
    }
    part[blockIdx.x * 512 + threadIdx.x] = s;
    part[blockIdx.x * 512 + 256 + threadIdx.x] = s2;
}

__global__ void reduce_affine_kernel(const float* __restrict__ part,
    const float* __restrict__ gg, const float* __restrict__ bb,
    float* __restrict__ ab, int CC, float invN)
{
    int c = threadIdx.x;
    if (c >= CC) return;
    float s = 0.f, s2 = 0.f;
    for (int blk = 0; blk < NSB; blk++) {
        const float* p = part + blk * 512;
        for (int g2 = c; g2 < 256; g2 += CC) { s += p[g2]; s2 += p[256 + g2]; }
    }
    float mu  = s * invN;
    float var = fmaf(-mu, mu, s2 * invN);
    float a = gg[c] * rsqrtf(var + EPSV);
    ab[c] = a;
    ab[CC + c] = fmaf(-mu, a, bb[c]);
}

// ---------------- ksum[m,k] = sum_c cb[m,k,c] ---------------------------------
__global__ void ksum_kernel(const float* __restrict__ cb, float* __restrict__ ks)
{
    __shared__ float sh[256];
    int row = blockIdx.x;  // 0..53
    sh[threadIdx.x] = cb[(size_t)row * CH + threadIdx.x];
    __syncthreads();
    for (int o = 128; o; o >>= 1) {
        if (threadIdx.x < o) sh[threadIdx.x] += sh[threadIdx.x + o];
        __syncthreads();
    }
    if (threadIdx.x == 0) ks[row] = sh[0];
}

// ---------------- q[n] = sum_k P[nbr[n,k], k] + stats -------------------------
__global__ void q_gather(const int* __restrict__ nbr, const float* __restrict__ P,
                         float* __restrict__ q, float* __restrict__ qpart)
{
    const int n = blockIdx.x * 256 + threadIdx.x;
    float s = 0.f;
#pragma unroll
    for (int k = 0; k < KK; k++) {
        int idx = nbr[(size_t)n * KK + k];
        s += P[(size_t)idx * KK + k];
    }
    q[n] = s;
    __shared__ float sh[512];
    sh[threadIdx.x] = s;
    sh[256 + threadIdx.x] = s * s;
    __syncthreads();
    for (int o = 128; o; o >>= 1) {
        if (threadIdx.x < o) {
            sh[threadIdx.x] += sh[threadIdx.x + o];
            sh[256 + threadIdx.x] += sh[256 + threadIdx.x + o];
        }
        __syncthreads();
    }
    if (threadIdx.x == 0) {
        qpart[blockIdx.x] = sh[0];
        qpart[NSB + blockIdx.x] = sh[256];
    }
}

__global__ void q_finalize(const float* __restrict__ qpart,
    const float* __restrict__ gq, const float* __restrict__ bq,
    float* __restrict__ qab, float invN)
{
    __shared__ float sh[2 * NSB];
    sh[threadIdx.x] = qpart[threadIdx.x];
    sh[NSB + threadIdx.x] = qpart[NSB + threadIdx.x];
    __syncthreads();
    for (int o = NSB / 2; o; o >>= 1) {
        if (threadIdx.x < o) {
            sh[threadIdx.x] += sh[threadIdx.x + o];
            sh[NSB + threadIdx.x] += sh[NSB + threadIdx.x + o];
        }
        __syncthreads();
    }
    if (threadIdx.x == 0) {
        float mu  = sh[0] * invN;
        float var = fmaf(-mu, mu, sh[NSB] * invN);
        float a = gq[0] * rsqrtf(var + EPSV);
        qab[0] = a;
        qab[1] = fmaf(-mu, a, bq[0]);
    }
}

// ---------------- choice = softmax( relu(bn(q))[nbr] @ ksum^T ) ---------------
__global__ void choice_kernel(const int* __restrict__ nbr, const float* __restrict__ q,
    const float* __restrict__ qab, const float* __restrict__ ks,
    float* __restrict__ choice)
{
    __shared__ float sks[2 * KK];
    if (threadIdx.x < 2 * KK) sks[threadIdx.x] = ks[threadIdx.x];
    __syncthreads();
    const int n = blockIdx.x * 256 + threadIdx.x;
    const float a = qab[0], b = qab[1];
    float l0 = 0.f, l1 = 0.f;
#pragma unroll
    for (int k = 0; k < KK; k++) {
        int idx = nbr[(size_t)n * KK + k];
        float qq = fmaxf(fmaf(q[idx], a, b), 0.f);
        l0 = fmaf(qq, sks[k], l0);
        l1 = fmaf(qq, sks[KK + k], l1);
    }
    float m = fmaxf(l0, l1);
    float e0 = expf(l0 - m), e1 = expf(l1 - m);
    float inv = 1.f / (e0 + e1);
    choice[(size_t)n * 2]     = e0 * inv;
    choice[(size_t)n * 2 + 1] = e1 * inv;
}

// ---------------- routed gather: the big one ----------------------------------
constexpr int RG_ROWS = 16;
constexpr int RG_SMEM = (2 * KK * CH + CH + CH + 2 * RG_ROWS + KK * RG_ROWS) * 4;

__global__ void __launch_bounds__(256) routed_gather(
    const float* __restrict__ v, const int* __restrict__ nbr,
    const float* __restrict__ choice, const float* __restrict__ cb,
    const float* __restrict__ vab, float* __restrict__ out1)
{
    extern __shared__ float sm[];
    float* s_cb = sm;                          // 2*27*256
    float* s_a  = s_cb + 2 * KK * CH;          // 256
    float* s_b  = s_a + CH;                    // 256
    float* s_ch = s_b + CH;                    // 32
    int*   s_idx = (int*)(s_ch + 2 * RG_ROWS); // 432
    const int tid = threadIdx.x;
    const int n0 = blockIdx.x * RG_ROWS;

    for (int i = tid; i < 2 * KK * CH; i += 256) s_cb[i] = cb[i];
    s_a[tid] = vab[tid];
    s_b[tid] = vab[CH + tid];
    for (int i = tid; i < 2 * RG_ROWS; i += 256) s_ch[i] = choice[(size_t)n0 * 2 + i];
    for (int i = tid; i < KK * RG_ROWS; i += 256) s_idx[i] = nbr[(size_t)n0 * KK + i];
    __syncthreads();

    const float a = s_a[tid], b = s_b[tid];
    for (int r = 0; r < RG_ROWS; r++) {
        const float c0 = s_ch[2 * r], c1 = s_ch[2 * r + 1];
        float acc = 0.f;
#pragma unroll
        for (int k = 0; k < KK; k++) {
            const int idx = s_idx[r * KK + k];
            float vv = __ldcg(&v[(size_t)idx * CH + tid]);   // L2-only, keep L1 for cb
            vv = fmaxf(fmaf(vv, a, b), 0.f);
            const float w = fmaf(c1, s_cb[KK * CH + k * CH + tid],
                                 c0 * s_cb[k * CH + tid]);
            acc = fmaf(vv, w, acc);
        }
        out1[(size_t)(n0 + r) * CH + tid] = acc;
    }
}

// ---------------- final: relu(bn(y)) + x --------------------------------------
__global__ void final_kernel(const float* __restrict__ y, const float* __restrict__ x,
    const float* __restrict__ yab, float* __restrict__ out)
{
    const int i = blockIdx.x * 256 + threadIdx.x;
    const int ch = i & (C - 1);
    const float a = yab[ch], b = yab[C + ch];
    out[i] = fmaxf(fmaf(y[i], a, b), 0.f) + x[i];
}

// ---------------- launch -------------------------------------------------------
extern "C" void kernel_launch(void* const* d_in, const int* in_sizes, int n_in,
                              void* d_out, int out_size)
{
    const float* x    = (const float*)d_in[0];
    const int*   nbr  = (const int*)  d_in[1];
    const float* Wv   = (const float*)d_in[2];
    const float* gv   = (const float*)d_in[3];
    const float* bv   = (const float*)d_in[4];
    const float* Wq   = (const float*)d_in[5];
    const float* gq   = (const float*)d_in[6];
    const float* bq   = (const float*)d_in[7];
    const float* cb   = (const float*)d_in[8];
    const float* Wout = (const float*)d_in[9];
    const float* go   = (const float*)d_in[10];
    const float* bo   = (const float*)d_in[11];
    float* out = (float*)d_out;
    const int N = in_sizes[0] / C;

    float *pv, *pP, *pq, *pout1, *py, *ppart, *pqpart, *pvab, *pqab, *pyab, *pksum, *pchoice;
    cudaGetSymbolAddress((void**)&pv,     g_v);
    cudaGetSymbolAddress((void**)&pP,     g_P);
    cudaGetSymbolAddress((void**)&pq,     g_q);
    cudaGetSymbolAddress((void**)&pout1,  g_out1);
    cudaGetSymbolAddress((void**)&py,     g_y);
    cudaGetSymbolAddress((void**)&ppart,  g_part);
    cudaGetSymbolAddress((void**)&pqpart, g_qpart);
    cudaGetSymbolAddress((void**)&pvab,   g_vab);
    cudaGetSymbolAddress((void**)&pqab,   g_qab);
    cudaGetSymbolAddress((void**)&pyab,   g_yab);
    cudaGetSymbolAddress((void**)&pksum,  g_ksum);
    cudaGetSymbolAddress((void**)&pchoice,g_choice);

    cudaFuncSetAttribute(routed_gather,
                         cudaFuncAttributeMaxDynamicSharedMemorySize, RG_SMEM);

    const float invN = 1.f / (float)N;

    // v = x @ Wv   (pre-BN)
    sgemm_kernel<128><<<dim3(N / 128, CH / 128), 256>>>(x, Wv, pv, CH);
    // P = x @ Wq^T
    p_gemm<<<N / 8, 256>>>(x, Wq, pP);
    // v BN stats -> affine
    colstats_kernel<<<NSB, 256>>>(pv, (size_t)N * CH / NSB, ppart);
    reduce_affine_kernel<<<1, 256>>>(ppart, gv, bv, pvab, CH, invN);
    // ksum from codebook
    ksum_kernel<<<MM * KK, 256>>>(cb, pksum);
    // q = gather-sum of P, with stats
    q_gather<<<N / 256, 256>>>(nbr, pP, pq, pqpart);
    q_finalize<<<1, NSB>>>(pqpart, gq, bq, pqab, invN);
    // routing weights
    choice_kernel<<<N / 256, 256>>>(nbr, pq, pqab, pksum, pchoice);
    // routed channelwise gather conv
    routed_gather<<<N / RG_ROWS, 256, RG_SMEM>>>(pv, nbr, pchoice, cb, pvab, pout1);
    // y = out1 @ Wout (pre-BN)
    sgemm_kernel<256><<<dim3(N / 128, 1), 256>>>(pout1, Wout, py, C);
    // y BN stats -> affine
    colstats_kernel<<<NSB, 256>>>(py, (size_t)N * C / NSB, ppart);
    reduce_affine_kernel<<<1, 256>>>(ppart, go, bo, pyab, C, invN);
    // out = relu(bn(y)) + x
    final_kernel<<<(size_t)N * C / 256, 256>>>(py, x, pyab, out);
}

// round 2
// speedup vs baseline: 1.5408x; 1.5408x over previous
#include <cuda_runtime.h>
#include <cuda_fp16.h>
#include <math.h>

#define EPSV 1e-5f

constexpr int C   = 128;
constexpr int CH  = 256;   // C*H
constexpr int KK  = 27;
constexpr int MM  = 2;
constexpr int NPTS = 131072;
constexpr int NSB = 512;   // stat partial blocks

// ---------------- device scratch (static; no allocations allowed) --------------
__device__ __half g_vh [(size_t)NPTS * CH];   // x @ Wv (pre-BN), fp16
__device__ float g_P   [(size_t)NPTS * KK];   // x @ Wq^T
__device__ float g_q   [NPTS];                // raw q (pre-BN)
__device__ float g_out1[(size_t)NPTS * CH];   // routed gather output
__device__ float g_y   [(size_t)NPTS * C];    // out1 @ Wout (pre-BN)
__device__ float g_part[NSB * 1024];          // column-stat partials
__device__ float g_qpart[2 * NSB];            // q stat partials
__device__ float g_vab [2 * CH];              // v BN affine (a, b)
__device__ float g_qab [2];                   // q BN affine
__device__ float g_yab [2 * C];               // y BN affine
__device__ float g_ksum[MM * KK];             // cb.sum(-1)
__device__ float g_choice[(size_t)NPTS * MM];

// ---------------- SGEMM: A[N,Kd] @ B[Kd,Ncols], 128x128 block, 8x8 microtile ---
template<int Kd, bool HALF_OUT>
__global__ void __launch_bounds__(256) sgemm_kernel(
    const float* __restrict__ A, const float* __restrict__ B,
    void* __restrict__ Cout, int Ncols)
{
    constexpr int BM = 128, BN = 128, BK = 16;
    __shared__ float As[BM][BK + 1];
    __shared__ float Bs[BK][BN];
    const int tid = threadIdx.x;
    const int tx = tid & 15, ty = tid >> 4;
    const int rowBase = blockIdx.x * BM;
    const int colBase = blockIdx.y * BN;

    float acc[8][8];
#pragma unroll
    for (int i = 0; i < 8; i++)
#pragma unroll
        for (int j = 0; j < 8; j++) acc[i][j] = 0.f;

    for (int k0 = 0; k0 < Kd; k0 += BK) {
#pragma unroll
        for (int it = 0; it < 2; it++) {
            int idx = it * 256 + tid;          // 0..511 float4 slots
            int r  = idx >> 2;                 // 0..127
            int kq = (idx & 3) << 2;           // 0,4,8,12
            float4 av = *reinterpret_cast<const float4*>(
                &A[(size_t)(rowBase + r) * Kd + k0 + kq]);
            As[r][kq + 0] = av.x; As[r][kq + 1] = av.y;
            As[r][kq + 2] = av.z; As[r][kq + 3] = av.w;
            int bk = idx >> 5;                 // 0..15
            int bc = (idx & 31) << 2;          // 0..124
            *reinterpret_cast<float4*>(&Bs[bk][bc]) =
                *reinterpret_cast<const float4*>(
                    &B[(size_t)(k0 + bk) * Ncols + colBase + bc]);
        }
        __syncthreads();
#pragma unroll
        for (int k = 0; k < BK; k++) {
            float ra[8], rb[8];
#pragma unroll
            for (int i = 0; i < 8; i++) ra[i] = As[ty * 8 + i][k];
            float4 b0 = *reinterpret_cast<const float4*>(&Bs[k][tx * 8]);
            float4 b1 = *reinterpret_cast<const float4*>(&Bs[k][tx * 8 + 4]);
            rb[0] = b0.x; rb[1] = b0.y; rb[2] = b0.z; rb[3] = b0.w;
            rb[4] = b1.x; rb[5] = b1.y; rb[6] = b1.z; rb[7] = b1.w;
#pragma unroll
            for (int i = 0; i < 8; i++)
#pragma unroll
                for (int j = 0; j < 8; j++)
                    acc[i][j] = fmaf(ra[i], rb[j], acc[i][j]);
        }
        __syncthreads();
    }
#pragma unroll
    for (int i = 0; i < 8; i++) {
        size_t r = (size_t)rowBase + ty * 8 + i;
        if constexpr (HALF_OUT) {
            __half* Cm = (__half*)Cout;
            __half2 h[4];
            h[0] = __floats2half2_rn(acc[i][0], acc[i][1]);
            h[1] = __floats2half2_rn(acc[i][2], acc[i][3]);
            h[2] = __floats2half2_rn(acc[i][4], acc[i][5]);
            h[3] = __floats2half2_rn(acc[i][6], acc[i][7]);
            *reinterpret_cast<int4*>(&Cm[r * Ncols + colBase + tx * 8]) =
                *reinterpret_cast<int4*>(h);
        } else {
            float* Cm = (float*)Cout;
            float4* o = reinterpret_cast<float4*>(&Cm[r * Ncols + colBase + tx * 8]);
            o[0] = make_float4(acc[i][0], acc[i][1], acc[i][2], acc[i][3]);
            o[1] = make_float4(acc[i][4], acc[i][5], acc[i][6], acc[i][7]);
        }
    }
}

// ---------------- P = x @ Wq^T : one warp per row, Wq [27,128] in shared -------
__global__ void __launch_bounds__(256) p_gemm(
    const float* __restrict__ x, const float* __restrict__ Wq,
    float* __restrict__ P)
{
    __shared__ float wqs[KK * C];
    for (int i = threadIdx.x; i < KK * C; i += 256) wqs[i] = Wq[i];
    __syncthreads();
    const int warp = threadIdx.x >> 5, lane = threadIdx.x & 31;
    const int row = blockIdx.x * 8 + warp;
    float4 xv = reinterpret_cast<const float4*>(x + (size_t)row * C)[lane];
#pragma unroll
    for (int k = 0; k < KK; k++) {
        float4 w = reinterpret_cast<const float4*>(wqs + k * C)[lane];
        float d = xv.x * w.x + xv.y * w.y + xv.z * w.z + xv.w * w.w;
#pragma unroll
        for (int o = 16; o; o >>= 1) d += __shfl_xor_sync(0xFFFFFFFFu, d, o);
        if (lane == 0) P[(size_t)row * KK + k] = d;
    }
}

// ---------------- column stats (fp16 data): deterministic two-pass -------------
// thread t accumulates channel pair (2*(t&127), 2*(t&127)+1) over its rows.
// partial layout per block (1024 floats): [0:256)=s_lo per thread,
// [256:512)=s2_lo, [512:768)=s_hi, [768:1024)=s2_hi.
__global__ void colstats_half(const __half2* __restrict__ data, int rowsPerBlock,
                              float* __restrict__ part)
{
    const int r0 = blockIdx.x * rowsPerBlock;
    const int t = threadIdx.x;
    const int col = t & 127;
    const int rOff = t >> 7;
    float sl = 0.f, sl2 = 0.f, sh = 0.f, sh2 = 0.f;
    for (int r = r0 + rOff; r < r0 + rowsPerBlock; r += 2) {
        float2 v = __half22float2(data[(size_t)r * 128 + col]);
        sl += v.x; sl2 = fmaf(v.x, v.x, sl2);
        sh += v.y; sh2 = fmaf(v.y, v.y, sh2);
    }
    float* p = part + (size_t)blockIdx.x * 1024;
    p[t] = sl; p[256 + t] = sl2; p[512 + t] = sh; p[768 + t] = sh2;
}

// reduce for v (CH=256 channels, half layout): one block per channel
__global__ void reduce_affine_v(const float* __restrict__ part,
    const float* __restrict__ gg, const float* __restrict__ bb,
    float* __restrict__ ab, float invN)
{
    const int c = blockIdx.x;
    const int m = c >> 1;
    const int offS = (c & 1) * 512;
    float s = 0.f, s2 = 0.f;
    for (int blk = threadIdx.x; blk < NSB; blk += 256) {
        const float* p = part + (size_t)blk * 1024;
        s  += p[offS + m] + p[offS + m + 128];
        s2 += p[offS + 256 + m] + p[offS + 256 + m + 128];
    }
    __shared__ float shm[512];
    shm[threadIdx.x] = s; shm[256 + threadIdx.x] = s2;
    __syncthreads();
    for (int o = 128; o; o >>= 1) {
        if (threadIdx.x < o) {
            shm[threadIdx.x] += shm[threadIdx.x + o];
            shm[256 + threadIdx.x] += shm[256 + threadIdx.x + o];
        }
        __syncthreads();
    }
    if (threadIdx.x == 0) {
        float mu  = shm[0] * invN;
        float var = fmaf(-mu, mu, shm[256] * invN);
        float a = gg[c] * rsqrtf(var + EPSV);
        ab[c] = a;
        ab[CH + c] = fmaf(-mu, a, bb[c]);
    }
}

// ---------------- column stats (fp32 data, for y) ------------------------------
__global__ void colstats_f32(const float* __restrict__ data, size_t perBlock,
                             float* __restrict__ part)
{
    size_t base = perBlock * blockIdx.x;
    float s = 0.f, s2 = 0.f;
    for (size_t i = base + threadIdx.x; i < base + perBlock; i += 256) {
        float v = data[i];
        s += v; s2 = fmaf(v, v, s2);
    }
    float* p = part + (size_t)blockIdx.x * 1024;
    p[threadIdx.x] = s;
    p[256 + threadIdx.x] = s2;
}

// reduce for y (C=128 channels, fp32 layout: channel = slot mod 128)
__global__ void reduce_affine_y(const float* __restrict__ part,
    const float* __restrict__ gg, const float* __restrict__ bb,
    float* __restrict__ ab, float invN)
{
    const int c = blockIdx.x;
    float s = 0.f, s2 = 0.f;
    for (int blk = threadIdx.x; blk < NSB; blk += 256) {
        const float* p = part + (size_t)blk * 1024;
        s  += p[c] + p[c + 128];
        s2 += p[256 + c] + p[256 + c + 128];
    }
    __shared__ float shm[512];
    shm[threadIdx.x] = s; shm[256 + threadIdx.x] = s2;
    __syncthreads();
    for (int o = 128; o; o >>= 1) {
        if (threadIdx.x < o) {
            shm[threadIdx.x] += shm[threadIdx.x + o];
            shm[256 + threadIdx.x] += shm[256 + threadIdx.x + o];
        }
        __syncthreads();
    }
    if (threadIdx.x == 0) {
        float mu  = shm[0] * invN;
        float var = fmaf(-mu, mu, shm[256] * invN);
        float a = gg[c] * rsqrtf(var + EPSV);
        ab[c] = a;
        ab[C + c] = fmaf(-mu, a, bb[c]);
    }
}

// ---------------- ksum[m,k] = sum_c cb[m,k,c] ---------------------------------
__global__ void ksum_kernel(const float* __restrict__ cb, float* __restrict__ ks)
{
    __shared__ float sh[256];
    int row = blockIdx.x;  // 0..53
    sh[threadIdx.x] = cb[(size_t)row * CH + threadIdx.x];
    __syncthreads();
    for (int o = 128; o; o >>= 1) {
        if (threadIdx.x < o) sh[threadIdx.x] += sh[threadIdx.x + o];
        __syncthreads();
    }
    if (threadIdx.x == 0) ks[row] = sh[0];
}

// ---------------- q[n] = sum_k P[nbr[n,k], k] + stats -------------------------
__global__ void q_gather(const int* __restrict__ nbr, const float* __restrict__ P,
                         float* __restrict__ q, float* __restrict__ qpart)
{
    const int n = blockIdx.x * 256 + threadIdx.x;
    float s = 0.f;
#pragma unroll
    for (int k = 0; k < KK; k++) {
        int idx = nbr[(size_t)n * KK + k];
        s += P[(size_t)idx * KK + k];
    }
    q[n] = s;
    __shared__ float sh[512];
    sh[threadIdx.x] = s;
    sh[256 + threadIdx.x] = s * s;
    __syncthreads();
    for (int o = 128; o; o >>= 1) {
        if (threadIdx.x < o) {
            sh[threadIdx.x] += sh[threadIdx.x + o];
            sh[256 + threadIdx.x] += sh[256 + threadIdx.x + o];
        }
        __syncthreads();
    }
    if (threadIdx.x == 0) {
        qpart[blockIdx.x] = sh[0];
        qpart[NSB + blockIdx.x] = sh[256];
    }
}

__global__ void q_finalize(const float* __restrict__ qpart,
    const float* __restrict__ gq, const float* __restrict__ bq,
    float* __restrict__ qab, float invN)
{
    __shared__ float sh[2 * NSB];
    sh[threadIdx.x] = qpart[threadIdx.x];
    sh[NSB + threadIdx.x] = qpart[NSB + threadIdx.x];
    __syncthreads();
    for (int o = NSB / 2; o; o >>= 1) {
        if (threadIdx.x < o) {
            sh[threadIdx.x] += sh[threadIdx.x + o];
            sh[NSB + threadIdx.x] += sh[NSB + threadIdx.x + o];
        }
        __syncthreads();
    }
    if (threadIdx.x == 0) {
        float mu  = sh[0] * invN;
        float var = fmaf(-mu, mu, sh[NSB] * invN);
        float a = gq[0] * rsqrtf(var + EPSV);
        qab[0] = a;
        qab[1] = fmaf(-mu, a, bq[0]);
    }
}

// ---------------- choice = softmax( relu(bn(q))[nbr] @ ksum^T ) ---------------
__global__ void choice_kernel(const int* __restrict__ nbr, const float* __restrict__ q,
    const float* __restrict__ qab, const float* __restrict__ ks,
    float* __restrict__ choice)
{
    __shared__ float sks[2 * KK];
    if (threadIdx.x < 2 * KK) sks[threadIdx.x] = ks[threadIdx.x];
    __syncthreads();
    const int n = blockIdx.x * 256 + threadIdx.x;
    const float a = qab[0], b = qab[1];
    float l0 = 0.f, l1 = 0.f;
#pragma unroll
    for (int k = 0; k < KK; k++) {
        int idx = nbr[(size_t)n * KK + k];
        float qq = fmaxf(fmaf(q[idx], a, b), 0.f);
        l0 = fmaf(qq, sks[k], l0);
        l1 = fmaf(qq, sks[KK + k], l1);
    }
    float m = fmaxf(l0, l1);
    float e0 = expf(l0 - m), e1 = expf(l1 - m);
    float inv = 1.f / (e0 + e1);
    choice[(size_t)n * 2]     = e0 * inv;
    choice[(size_t)n * 2 + 1] = e1 * inv;
}

// ---------------- routed gather: the big one (fp16 v, half2 per thread) --------
constexpr int RG_ROWS = 32;
constexpr int RG_SMEM = (2 * KK * CH + CH + CH + 2 * RG_ROWS + KK * RG_ROWS) * 4;

__global__ void __launch_bounds__(256) routed_gather(
    const __half2* __restrict__ vh, const int* __restrict__ nbr,
    const float* __restrict__ choice, const float* __restrict__ cb,
    const float* __restrict__ vab, float* __restrict__ out1)
{
    extern __shared__ float sm[];
    float* s_cb = sm;                          // 2*27*256
    float* s_a  = s_cb + 2 * KK * CH;          // 256
    float* s_b  = s_a + CH;                    // 256
    float* s_ch = s_b + CH;                    // 2*RG_ROWS
    int*   s_idx = (int*)(s_ch + 2 * RG_ROWS); // KK*RG_ROWS
    const int tid = threadIdx.x;
    const int grp = tid >> 7;        // 0/1: which of two concurrent rows
    const int c2  = tid & 127;       // half2 column (channel pair)
    const int n0 = blockIdx.x * RG_ROWS;

    for (int i = tid; i < 2 * KK * CH; i += 256) s_cb[i] = cb[i];
    s_a[tid] = vab[tid];
    s_b[tid] = vab[CH + tid];
    for (int i = tid; i < 2 * RG_ROWS; i += 256) s_ch[i] = choice[(size_t)n0 * 2 + i];
    for (int i = tid; i < KK * RG_ROWS; i += 256) s_idx[i] = nbr[(size_t)n0 * KK + i];
    __syncthreads();

    const float2 aa = reinterpret_cast<const float2*>(s_a)[c2];
    const float2 bb = reinterpret_cast<const float2*>(s_b)[c2];
    const float2* cb2 = reinterpret_cast<const float2*>(s_cb);

    for (int rr = 0; rr < RG_ROWS; rr += 2) {
        const int r = rr + grp;
        const float c0 = s_ch[2 * r], c1 = s_ch[2 * r + 1];
        float acc0 = 0.f, acc1 = 0.f;
#pragma unroll
        for (int k = 0; k < KK; k++) {
            const int idx = s_idx[r * KK + k];
            const __half2 hv = __ldcg(&vh[(size_t)idx * 128 + c2]);
            const float2 vv = __half22float2(hv);
            const float v0 = fmaxf(fmaf(vv.x, aa.x, bb.x), 0.f);
            const float v1 = fmaxf(fmaf(vv.y, aa.y, bb.y), 0.f);
            const float2 w0 = cb2[k * 128 + c2];
            const float2 w1 = cb2[KK * 128 + k * 128 + c2];
            acc0 = fmaf(v0, fmaf(c1, w1.x, c0 * w0.x), acc0);
            acc1 = fmaf(v1, fmaf(c1, w1.y, c0 * w0.y), acc1);
        }
        reinterpret_cast<float2*>(out1)[(size_t)(n0 + r) * 128 + c2] =
            make_float2(acc0, acc1);
    }
}

// ---------------- final: relu(bn(y)) + x --------------------------------------
__global__ void final_kernel(const float* __restrict__ y, const float* __restrict__ x,
    const float* __restrict__ yab, float* __restrict__ out)
{
    const int i = blockIdx.x * 256 + threadIdx.x;
    const int ch = i & (C - 1);
    const float a = yab[ch], b = yab[C + ch];
    out[i] = fmaxf(fmaf(y[i], a, b), 0.f) + x[i];
}

// ---------------- launch -------------------------------------------------------
extern "C" void kernel_launch(void* const* d_in, const int* in_sizes, int n_in,
                              void* d_out, int out_size)
{
    const float* x    = (const float*)d_in[0];
    const int*   nbr  = (const int*)  d_in[1];
    const float* Wv   = (const float*)d_in[2];
    const float* gv   = (const float*)d_in[3];
    const float* bv   = (const float*)d_in[4];
    const float* Wq   = (const float*)d_in[5];
    const float* gq   = (const float*)d_in[6];
    const float* bq   = (const float*)d_in[7];
    const float* cb   = (const float*)d_in[8];
    const float* Wout = (const float*)d_in[9];
    const float* go   = (const float*)d_in[10];
    const float* bo   = (const float*)d_in[11];
    float* out = (float*)d_out;
    const int N = in_sizes[0] / C;

    __half* pvh; float *pP, *pq, *pout1, *py, *ppart, *pqpart, *pvab, *pqab, *pyab, *pksum, *pchoice;
    cudaGetSymbolAddress((void**)&pvh,    g_vh);
    cudaGetSymbolAddress((void**)&pP,     g_P);
    cudaGetSymbolAddress((void**)&pq,     g_q);
    cudaGetSymbolAddress((void**)&pout1,  g_out1);
    cudaGetSymbolAddress((void**)&py,     g_y);
    cudaGetSymbolAddress((void**)&ppart,  g_part);
    cudaGetSymbolAddress((void**)&pqpart, g_qpart);
    cudaGetSymbolAddress((void**)&pvab,   g_vab);
    cudaGetSymbolAddress((void**)&pqab,   g_qab);
    cudaGetSymbolAddress((void**)&pyab,   g_yab);
    cudaGetSymbolAddress((void**)&pksum,  g_ksum);
    cudaGetSymbolAddress((void**)&pchoice,g_choice);

    cudaFuncSetAttribute(routed_gather,
                         cudaFuncAttributeMaxDynamicSharedMemorySize, RG_SMEM);

    const float invN = 1.f / (float)N;

    // v = x @ Wv  (pre-BN, fp16 storage)
    sgemm_kernel<128, true><<<dim3(N / 128, CH / 128), 256>>>(x, Wv, pvh, CH);
    // P = x @ Wq^T
    p_gemm<<<N / 8, 256>>>(x, Wq, pP);
    // v BN stats -> affine (parallel reduce)
    colstats_half<<<NSB, 256>>>((const __half2*)pvh, N / NSB, ppart);
    reduce_affine_v<<<CH, 256>>>(ppart, gv, bv, pvab, invN);
    // ksum from codebook
    ksum_kernel<<<MM * KK, 256>>>(cb, pksum);
    // q = gather-sum of P, with stats
    q_gather<<<N / 256, 256>>>(nbr, pP, pq, pqpart);
    q_finalize<<<1, NSB>>>(pqpart, gq, bq, pqab, invN);
    // routing weights
    choice_kernel<<<N / 256, 256>>>(nbr, pq, pqab, pksum, pchoice);
    // routed channelwise gather conv
    routed_gather<<<N / RG_ROWS, 256, RG_SMEM>>>(
        (const __half2*)pvh, nbr, pchoice, cb, pvab, pout1);
    // y = out1 @ Wout (pre-BN)
    sgemm_kernel<256, false><<<dim3(N / 128, 1), 256>>>(pout1, Wout, py, C);
    // y BN stats -> affine (parallel reduce)
    colstats_f32<<<NSB, 256>>>(py, (size_t)N * C / NSB, ppart);
    reduce_affine_y<<<C, 256>>>(ppart, go, bo, pyab, invN);
    // out = relu(bn(y)) + x
    final_kernel<<<(size_t)N * C / 256, 256>>>(py, x, pyab, out);
}

// round 3
// speedup vs baseline: 1.9777x; 1.2836x over previous
#include <cuda_runtime.h>
#include <cuda_fp16.h>
#include <math.h>

#define EPSV 1e-5f

constexpr int C   = 128;
constexpr int CH  = 256;   // C*H
constexpr int KK  = 27;
constexpr int MM  = 2;
constexpr int NPTS = 131072;
constexpr int NSB = 512;   // stat partial blocks

// ---------------- device scratch (static; no allocations allowed) --------------
__device__ __half g_vh [(size_t)NPTS * CH];   // x @ Wv (pre-BN), fp16
__device__ float g_P   [(size_t)NPTS * KK];   // x @ Wq^T
__device__ float g_q   [NPTS];                // raw q (pre-BN)
__device__ float g_out1[(size_t)NPTS * CH];   // routed gather output
__device__ float g_y   [(size_t)NPTS * C];    // out1 @ Wout (pre-BN)
__device__ float g_part[NSB * 1024];          // column-stat partials
__device__ float g_qpart[2 * NSB];            // q stat partials
__device__ float g_vab [2 * CH];              // v BN affine (a, b)
__device__ float g_qab [2];                   // q BN affine
__device__ float g_yab [2 * C];               // y BN affine
__device__ float g_ksum[MM * KK];             // cb.sum(-1)
__device__ float g_choice[(size_t)NPTS * MM];

// =====================================================================
// Split-fp16 tensor-core GEMM:  C[N,Ncols] = A[N,Kd] @ B[Kd,Ncols]
// fp32 inputs are split a = hi + lo (fp16 each); D += Ah*Bh + Ah*Bl + Al*Bh
// gives ~fp32 accuracy on HMMA pipes.
// Block: 256 thr (8 warps, 2x4), tile 128x128xBK32, mma m16n8k16.
// =====================================================================
constexpr int APITCH = 40;   // halves; row stride 80B -> conflict-free LDSM
constexpr int BPITCH = 136;  // halves; row stride 272B -> conflict-free LDSM

__device__ __forceinline__ void split2(float f, __half& hi, __half& lo) {
    hi = __float2half_rn(f);
    lo = __float2half_rn(f - __half2float(hi));
}

template<int Kd, bool HALF_OUT>
__global__ void __launch_bounds__(256) hgemm_split(
    const float* __restrict__ A, const float* __restrict__ B,
    void* __restrict__ Cout, int Ncols)
{
    __shared__ __align__(16) __half Ah[128 * APITCH];
    __shared__ __align__(16) __half Al[128 * APITCH];
    __shared__ __align__(16) __half Bh[32 * BPITCH];
    __shared__ __align__(16) __half Bl[32 * BPITCH];

    const int tid  = threadIdx.x;
    const int warp = tid >> 5, lane = tid & 31;
    const int wm = warp >> 2;       // 0..1 : 64-row slab
    const int wn = warp & 3;        // 0..3 : 32-col slab
    const int rowBase = blockIdx.x * 128;
    const int colBase = blockIdx.y * 128;

    float acc[4][4][4];             // [mtile][ntile][frag]
#pragma unroll
    for (int i = 0; i < 4; i++)
#pragma unroll
        for (int j = 0; j < 4; j++)
#pragma unroll
            for (int f = 0; f < 4; f++) acc[i][j][f] = 0.f;

    for (int k0 = 0; k0 < Kd; k0 += 32) {
        // ---- load + split A tile (128x32 fp32) ----
#pragma unroll
        for (int it = 0; it < 4; it++) {
            int idx = it * 256 + tid;        // 0..1023 float4 slots
            int r = idx >> 3, q = idx & 7;   // row, float4-in-row
            float4 av = *reinterpret_cast<const float4*>(
                &A[(size_t)(rowBase + r) * Kd + k0 + q * 4]);
            __half h0,l0,h1,l1,h2,l2,h3,l3;
            split2(av.x,h0,l0); split2(av.y,h1,l1);
            split2(av.z,h2,l2); split2(av.w,h3,l3);
            __half2* ph = reinterpret_cast<__half2*>(&Ah[r * APITCH + q * 4]);
            __half2* pl = reinterpret_cast<__half2*>(&Al[r * APITCH + q * 4]);
            ph[0] = __halves2half2(h0,h1); ph[1] = __halves2half2(h2,h3);
            pl[0] = __halves2half2(l0,l1); pl[1] = __halves2half2(l2,l3);
        }
        // ---- load + split B tile (32x128 fp32) ----
#pragma unroll
        for (int it = 0; it < 4; it++) {
            int idx = it * 256 + tid;
            int r = idx >> 5, q = idx & 31;
            float4 bv = *reinterpret_cast<const float4*>(
                &B[(size_t)(k0 + r) * Ncols + colBase + q * 4]);
            __half h0,l0,h1,l1,h2,l2,h3,l3;
            split2(bv.x,h0,l0); split2(bv.y,h1,l1);
            split2(bv.z,h2,l2); split2(bv.w,h3,l3);
            __half2* ph = reinterpret_cast<__half2*>(&Bh[r * BPITCH + q * 4]);
            __half2* pl = reinterpret_cast<__half2*>(&Bl[r * BPITCH + q * 4]);
            ph[0] = __halves2half2(h0,h1); ph[1] = __halves2half2(h2,h3);
            pl[0] = __halves2half2(l0,l1); pl[1] = __halves2half2(l2,l3);
        }
        __syncthreads();

#pragma unroll
        for (int ks = 0; ks < 32; ks += 16) {
            // A frags: ldmatrix x4 per mtile (16x16)
            unsigned ah[4][4], al[4][4];
#pragma unroll
            for (int mt = 0; mt < 4; mt++) {
                int row = wm * 64 + mt * 16 + (lane & 15);
                int col = ks + (lane >> 4) * 8;
                unsigned addrH = (unsigned)__cvta_generic_to_shared(&Ah[row * APITCH + col]);
                unsigned addrL = (unsigned)__cvta_generic_to_shared(&Al[row * APITCH + col]);
                asm volatile("ldmatrix.sync.aligned.m8n8.x4.shared.b16 {%0,%1,%2,%3}, [%4];"
                    : "=r"(ah[mt][0]),"=r"(ah[mt][1]),"=r"(ah[mt][2]),"=r"(ah[mt][3])
                    : "r"(addrH));
                asm volatile("ldmatrix.sync.aligned.m8n8.x4.shared.b16 {%0,%1,%2,%3}, [%4];"
                    : "=r"(al[mt][0]),"=r"(al[mt][1]),"=r"(al[mt][2]),"=r"(al[mt][3])
                    : "r"(addrL));
            }
            // B frags: ldmatrix x4 trans covers two ntiles (16x16)
            unsigned bh[4][2], bl[4][2];
#pragma unroll
            for (int pr = 0; pr < 2; pr++) {
                int krow = ks + (lane & 15);
                int col = wn * 32 + pr * 16 + (lane >> 4) * 8;
                unsigned addrH = (unsigned)__cvta_generic_to_shared(&Bh[krow * BPITCH + col]);
                unsigned addrL = (unsigned)__cvta_generic_to_shared(&Bl[krow * BPITCH + col]);
                asm volatile("ldmatrix.sync.aligned.m8n8.x4.trans.shared.b16 {%0,%1,%2,%3}, [%4];"
                    : "=r"(bh[pr*2][0]),"=r"(bh[pr*2][1]),"=r"(bh[pr*2+1][0]),"=r"(bh[pr*2+1][1])
                    : "r"(addrH));
                asm volatile("ldmatrix.sync.aligned.m8n8.x4.trans.shared.b16 {%0,%1,%2,%3}, [%4];"
                    : "=r"(bl[pr*2][0]),"=r"(bl[pr*2][1]),"=r"(bl[pr*2+1][0]),"=r"(bl[pr*2+1][1])
                    : "r"(addrL));
            }
#pragma unroll
            for (int mt = 0; mt < 4; mt++)
#pragma unroll
                for (int nt = 0; nt < 4; nt++) {
                    float* d = acc[mt][nt];
#define MMA(Af, Bf) \
    asm volatile("mma.sync.aligned.m16n8k16.row.col.f32.f16.f16.f32 " \
        "{%0,%1,%2,%3}, {%4,%5,%6,%7}, {%8,%9}, {%0,%1,%2,%3};" \
        : "+f"(d[0]),"+f"(d[1]),"+f"(d[2]),"+f"(d[3]) \
        : "r"(Af[0]),"r"(Af[1]),"r"(Af[2]),"r"(Af[3]), "r"(Bf[0]),"r"(Bf[1]))
                    MMA(ah[mt], bh[nt]);
                    MMA(ah[mt], bl[nt]);
                    MMA(al[mt], bh[nt]);
#undef MMA
                }
        }
        __syncthreads();
    }

    // ---- epilogue ----
    const int g = lane >> 2, tg = lane & 3;
#pragma unroll
    for (int mt = 0; mt < 4; mt++)
#pragma unroll
        for (int nt = 0; nt < 4; nt++) {
            size_t row = (size_t)rowBase + wm * 64 + mt * 16 + g;
            int col = colBase + wn * 32 + nt * 8 + tg * 2;
            float* d = acc[mt][nt];
            if constexpr (HALF_OUT) {
                __half* Cm = (__half*)Cout;
                *reinterpret_cast<__half2*>(&Cm[row * Ncols + col]) =
                    __floats2half2_rn(d[0], d[1]);
                *reinterpret_cast<__half2*>(&Cm[(row + 8) * Ncols + col]) =
                    __floats2half2_rn(d[2], d[3]);
            } else {
                float* Cm = (float*)Cout;
                *reinterpret_cast<float2*>(&Cm[row * Ncols + col]) =
                    make_float2(d[0], d[1]);
                *reinterpret_cast<float2*>(&Cm[(row + 8) * Ncols + col]) =
                    make_float2(d[2], d[3]);
            }
        }
}

// ---------------- P = x @ Wq^T : one warp per row, Wq [27,128] in shared -------
__global__ void __launch_bounds__(256) p_gemm(
    const float* __restrict__ x, const float* __restrict__ Wq,
    float* __restrict__ P)
{
    __shared__ float wqs[KK * C];
    for (int i = threadIdx.x; i < KK * C; i += 256) wqs[i] = Wq[i];
    __syncthreads();
    const int warp = threadIdx.x >> 5, lane = threadIdx.x & 31;
    const int row = blockIdx.x * 8 + warp;
    float4 xv = reinterpret_cast<const float4*>(x + (size_t)row * C)[lane];
#pragma unroll
    for (int k = 0; k < KK; k++) {
        float4 w = reinterpret_cast<const float4*>(wqs + k * C)[lane];
        float d = xv.x * w.x + xv.y * w.y + xv.z * w.z + xv.w * w.w;
#pragma unroll
        for (int o = 16; o; o >>= 1) d += __shfl_xor_sync(0xFFFFFFFFu, d, o);
        if (lane == 0) P[(size_t)row * KK + k] = d;
    }
}

// ---------------- column stats (fp16 data): deterministic two-pass -------------
__global__ void colstats_half(const __half2* __restrict__ data, int rowsPerBlock,
                              float* __restrict__ part)
{
    const int r0 = blockIdx.x * rowsPerBlock;
    const int t = threadIdx.x;
    const int col = t & 127;
    const int rOff = t >> 7;
    float sl = 0.f, sl2 = 0.f, sh = 0.f, sh2 = 0.f;
    for (int r = r0 + rOff; r < r0 + rowsPerBlock; r += 2) {
        float2 v = __half22float2(data[(size_t)r * 128 + col]);
        sl += v.x; sl2 = fmaf(v.x, v.x, sl2);
        sh += v.y; sh2 = fmaf(v.y, v.y, sh2);
    }
    float* p = part + (size_t)blockIdx.x * 1024;
    p[t] = sl; p[256 + t] = sl2; p[512 + t] = sh; p[768 + t] = sh2;
}

__global__ void reduce_affine_v(const float* __restrict__ part,
    const float* __restrict__ gg, const float* __restrict__ bb,
    float* __restrict__ ab, float invN)
{
    const int c = blockIdx.x;
    const int m = c >> 1;
    const int offS = (c & 1) * 512;
    float s = 0.f, s2 = 0.f;
    for (int blk = threadIdx.x; blk < NSB; blk += 256) {
        const float* p = part + (size_t)blk * 1024;
        s  += p[offS + m] + p[offS + m + 128];
        s2 += p[offS + 256 + m] + p[offS + 256 + m + 128];
    }
    __shared__ float shm[512];
    shm[threadIdx.x] = s; shm[256 + threadIdx.x] = s2;
    __syncthreads();
    for (int o = 128; o; o >>= 1) {
        if (threadIdx.x < o) {
            shm[threadIdx.x] += shm[threadIdx.x + o];
            shm[256 + threadIdx.x] += shm[256 + threadIdx.x + o];
        }
        __syncthreads();
    }
    if (threadIdx.x == 0) {
        float mu  = shm[0] * invN;
        float var = fmaf(-mu, mu, shm[256] * invN);
        float a = gg[c] * rsqrtf(var + EPSV);
        ab[c] = a;
        ab[CH + c] = fmaf(-mu, a, bb[c]);
    }
}

__global__ void colstats_f32(const float* __restrict__ data, size_t perBlock,
                             float* __restrict__ part)
{
    size_t base = perBlock * blockIdx.x;
    float s = 0.f, s2 = 0.f;
    for (size_t i = base + threadIdx.x; i < base + perBlock; i += 256) {
        float v = data[i];
        s += v; s2 = fmaf(v, v, s2);
    }
    float* p = part + (size_t)blockIdx.x * 1024;
    p[threadIdx.x] = s;
    p[256 + threadIdx.x] = s2;
}

__global__ void reduce_affine_y(const float* __restrict__ part,
    const float* __restrict__ gg, const float* __restrict__ bb,
    float* __restrict__ ab, float invN)
{
    const int c = blockIdx.x;
    float s = 0.f, s2 = 0.f;
    for (int blk = threadIdx.x; blk < NSB; blk += 256) {
        const float* p = part + (size_t)blk * 1024;
        s  += p[c] + p[c + 128];
        s2 += p[256 + c] + p[256 + c + 128];
    }
    __shared__ float shm[512];
    shm[threadIdx.x] = s; shm[256 + threadIdx.x] = s2;
    __syncthreads();
    for (int o = 128; o; o >>= 1) {
        if (threadIdx.x < o) {
            shm[threadIdx.x] += shm[threadIdx.x + o];
            shm[256 + threadIdx.x] += shm[256 + threadIdx.x + o];
        }
        __syncthreads();
    }
    if (threadIdx.x == 0) {
        float mu  = shm[0] * invN;
        float var = fmaf(-mu, mu, shm[256] * invN);
        float a = gg[c] * rsqrtf(var + EPSV);
        ab[c] = a;
        ab[C + c] = fmaf(-mu, a, bb[c]);
    }
}

// ---------------- ksum[m,k] = sum_c cb[m,k,c] ---------------------------------
__global__ void ksum_kernel(const float* __restrict__ cb, float* __restrict__ ks)
{
    __shared__ float sh[256];
    int row = blockIdx.x;
    sh[threadIdx.x] = cb[(size_t)row * CH + threadIdx.x];
    __syncthreads();
    for (int o = 128; o; o >>= 1) {
        if (threadIdx.x < o) sh[threadIdx.x] += sh[threadIdx.x + o];
        __syncthreads();
    }
    if (threadIdx.x == 0) ks[row] = sh[0];
}

// ---------------- q[n] = sum_k P[nbr[n,k], k] + stats -------------------------
__global__ void q_gather(const int* __restrict__ nbr, const float* __restrict__ P,
                         float* __restrict__ q, float* __restrict__ qpart)
{
    const int n = blockIdx.x * 256 + threadIdx.x;
    float s = 0.f;
#pragma unroll
    for (int k = 0; k < KK; k++) {
        int idx = nbr[(size_t)n * KK + k];
        s += P[(size_t)idx * KK + k];
    }
    q[n] = s;
    __shared__ float sh[512];
    sh[threadIdx.x] = s;
    sh[256 + threadIdx.x] = s * s;
    __syncthreads();
    for (int o = 128; o; o >>= 1) {
        if (threadIdx.x < o) {
            sh[threadIdx.x] += sh[threadIdx.x + o];
            sh[256 + threadIdx.x] += sh[256 + threadIdx.x + o];
        }
        __syncthreads();
    }
    if (threadIdx.x == 0) {
        qpart[blockIdx.x] = sh[0];
        qpart[NSB + blockIdx.x] = sh[256];
    }
}

__global__ void q_finalize(const float* __restrict__ qpart,
    const float* __restrict__ gq, const float* __restrict__ bq,
    float* __restrict__ qab, float invN)
{
    __shared__ float sh[2 * NSB];
    sh[threadIdx.x] = qpart[threadIdx.x];
    sh[NSB + threadIdx.x] = qpart[NSB + threadIdx.x];
    __syncthreads();
    for (int o = NSB / 2; o; o >>= 1) {
        if (threadIdx.x < o) {
            sh[threadIdx.x] += sh[threadIdx.x + o];
            sh[NSB + threadIdx.x] += sh[NSB + threadIdx.x + o];
        }
        __syncthreads();
    }
    if (threadIdx.x == 0) {
        float mu  = sh[0] * invN;
        float var = fmaf(-mu, mu, sh[NSB] * invN);
        float a = gq[0] * rsqrtf(var + EPSV);
        qab[0] = a;
        qab[1] = fmaf(-mu, a, bq[0]);
    }
}

// ---------------- choice = softmax( relu(bn(q))[nbr] @ ksum^T ) ---------------
__global__ void choice_kernel(const int* __restrict__ nbr, const float* __restrict__ q,
    const float* __restrict__ qab, const float* __restrict__ ks,
    float* __restrict__ choice)
{
    __shared__ float sks[2 * KK];
    if (threadIdx.x < 2 * KK) sks[threadIdx.x] = ks[threadIdx.x];
    __syncthreads();
    const int n = blockIdx.x * 256 + threadIdx.x;
    const float a = qab[0], b = qab[1];
    float l0 = 0.f, l1 = 0.f;
#pragma unroll
    for (int k = 0; k < KK; k++) {
        int idx = nbr[(size_t)n * KK + k];
        float qq = fmaxf(fmaf(q[idx], a, b), 0.f);
        l0 = fmaf(qq, sks[k], l0);
        l1 = fmaf(qq, sks[KK + k], l1);
    }
    float m = fmaxf(l0, l1);
    float e0 = expf(l0 - m), e1 = expf(l1 - m);
    float inv = 1.f / (e0 + e1);
    choice[(size_t)n * 2]     = e0 * inv;
    choice[(size_t)n * 2 + 1] = e1 * inv;
}

// ---------------- routed gather (fp16 v, half2 per thread) ---------------------
constexpr int RG_ROWS = 32;
constexpr int RG_SMEM = (2 * KK * CH + CH + CH + 2 * RG_ROWS + KK * RG_ROWS) * 4;

__global__ void __launch_bounds__(256) routed_gather(
    const __half2* __restrict__ vh, const int* __restrict__ nbr,
    const float* __restrict__ choice, const float* __restrict__ cb,
    const float* __restrict__ vab, float* __restrict__ out1)
{
    extern __shared__ float sm[];
    float* s_cb = sm;
    float* s_a  = s_cb + 2 * KK * CH;
    float* s_b  = s_a + CH;
    float* s_ch = s_b + CH;
    int*   s_idx = (int*)(s_ch + 2 * RG_ROWS);
    const int tid = threadIdx.x;
    const int grp = tid >> 7;
    const int c2  = tid & 127;
    const int n0 = blockIdx.x * RG_ROWS;

    for (int i = tid; i < 2 * KK * CH; i += 256) s_cb[i] = cb[i];
    s_a[tid] = vab[tid];
    s_b[tid] = vab[CH + tid];
    for (int i = tid; i < 2 * RG_ROWS; i += 256) s_ch[i] = choice[(size_t)n0 * 2 + i];
    for (int i = tid; i < KK * RG_ROWS; i += 256) s_idx[i] = nbr[(size_t)n0 * KK + i];
    __syncthreads();

    const float2 aa = reinterpret_cast<const float2*>(s_a)[c2];
    const float2 bb = reinterpret_cast<const float2*>(s_b)[c2];
    const float2* cb2 = reinterpret_cast<const float2*>(s_cb);

    for (int rr = 0; rr < RG_ROWS; rr += 2) {
        const int r = rr + grp;
        const float c0 = s_ch[2 * r], c1 = s_ch[2 * r + 1];
        float acc0 = 0.f, acc1 = 0.f;
#pragma unroll
        for (int k = 0; k < KK; k++) {
            const int idx = s_idx[r * KK + k];
            const __half2 hv = __ldcg(&vh[(size_t)idx * 128 + c2]);
            const float2 vv = __half22float2(hv);
            const float v0 = fmaxf(fmaf(vv.x, aa.x, bb.x), 0.f);
            const float v1 = fmaxf(fmaf(vv.y, aa.y, bb.y), 0.f);
            const float2 w0 = cb2[k * 128 + c2];
            const float2 w1 = cb2[KK * 128 + k * 128 + c2];
            acc0 = fmaf(v0, fmaf(c1, w1.x, c0 * w0.x), acc0);
            acc1 = fmaf(v1, fmaf(c1, w1.y, c0 * w0.y), acc1);
        }
        reinterpret_cast<float2*>(out1)[(size_t)(n0 + r) * 128 + c2] =
            make_float2(acc0, acc1);
    }
}

// ---------------- final: relu(bn(y)) + x --------------------------------------
__global__ void final_kernel(const float* __restrict__ y, const float* __restrict__ x,
    const float* __restrict__ yab, float* __restrict__ out)
{
    const int i = blockIdx.x * 256 + threadIdx.x;
    const int ch = i & (C - 1);
    const float a = yab[ch], b = yab[C + ch];
    out[i] = fmaxf(fmaf(y[i], a, b), 0.f) + x[i];
}

// ---------------- launch -------------------------------------------------------
extern "C" void kernel_launch(void* const* d_in, const int* in_sizes, int n_in,
                              void* d_out, int out_size)
{
    const float* x    = (const float*)d_in[0];
    const int*   nbr  = (const int*)  d_in[1];
    const float* Wv   = (const float*)d_in[2];
    const float* gv   = (const float*)d_in[3];
    const float* bv   = (const float*)d_in[4];
    const float* Wq   = (const float*)d_in[5];
    const float* gq   = (const float*)d_in[6];
    const float* bq   = (const float*)d_in[7];
    const float* cb   = (const float*)d_in[8];
    const float* Wout = (const float*)d_in[9];
    const float* go   = (const float*)d_in[10];
    const float* bo   = (const float*)d_in[11];
    float* out = (float*)d_out;
    const int N = in_sizes[0] / C;

    __half* pvh; float *pP, *pq, *pout1, *py, *ppart, *pqpart, *pvab, *pqab, *pyab, *pksum, *pchoice;
    cudaGetSymbolAddress((void**)&pvh,    g_vh);
    cudaGetSymbolAddress((void**)&pP,     g_P);
    cudaGetSymbolAddress((void**)&pq,     g_q);
    cudaGetSymbolAddress((void**)&pout1,  g_out1);
    cudaGetSymbolAddress((void**)&py,     g_y);
    cudaGetSymbolAddress((void**)&ppart,  g_part);
    cudaGetSymbolAddress((void**)&pqpart, g_qpart);
    cudaGetSymbolAddress((void**)&pvab,   g_vab);
    cudaGetSymbolAddress((void**)&pqab,   g_qab);
    cudaGetSymbolAddress((void**)&pyab,   g_yab);
    cudaGetSymbolAddress((void**)&pksum,  g_ksum);
    cudaGetSymbolAddress((void**)&pchoice,g_choice);

    cudaFuncSetAttribute(routed_gather,
                         cudaFuncAttributeMaxDynamicSharedMemorySize, RG_SMEM);

    const float invN = 1.f / (float)N;

    // v = x @ Wv  (tensor cores, fp16 split, fp16 storage)
    hgemm_split<128, true><<<dim3(N / 128, CH / 128), 256>>>(x, Wv, pvh, CH);
    // P = x @ Wq^T
    p_gemm<<<N / 8, 256>>>(x, Wq, pP);
    // v BN stats -> affine
    colstats_half<<<NSB, 256>>>((const __half2*)pvh, N / NSB, ppart);
    reduce_affine_v<<<CH, 256>>>(ppart, gv, bv, pvab, invN);
    // ksum from codebook
    ksum_kernel<<<MM * KK, 256>>>(cb, pksum);
    // q = gather-sum of P, with stats
    q_gather<<<N / 256, 256>>>(nbr, pP, pq, pqpart);
    q_finalize<<<1, NSB>>>(pqpart, gq, bq, pqab, invN);
    // routing weights
    choice_kernel<<<N / 256, 256>>>(nbr, pq, pqab, pksum, pchoice);
    // routed channelwise gather conv
    routed_gather<<<N / RG_ROWS, 256, RG_SMEM>>>(
        (const __half2*)pvh, nbr, pchoice, cb, pvab, pout1);
    // y = out1 @ Wout (tensor cores, fp16 split, fp32 out)
    hgemm_split<256, false><<<dim3(N / 128, 1), 256>>>(pout1, Wout, py, C);
    // y BN stats -> affine
    colstats_f32<<<NSB, 256>>>(py, (size_t)N * C / NSB, ppart);
    reduce_affine_y<<<C, 256>>>(ppart, go, bo, pyab, invN);
    // out = relu(bn(y)) + x
    final_kernel<<<(size_t)N * C / 256, 256>>>(py, x, pyab, out);
}

// round 4
// speedup vs baseline: 1.9785x; 1.0004x over previous
#include <cuda_runtime.h>
#include <cuda_fp16.h>
#include <math.h>

#define EPSV 1e-5f

constexpr int C   = 128;
constexpr int CH  = 256;   // C*H
constexpr int KK  = 27;
constexpr int MM  = 2;
constexpr int NPTS = 131072;
constexpr int NSB = 512;   // stat partial blocks

// ---------------- device scratch (static; no allocations allowed) --------------
__device__ __half g_vh [(size_t)NPTS * CH];   // x @ Wv (pre-BN), fp16
__device__ __half g_xh [(size_t)NPTS * C];    // x hi plane
__device__ __half g_xl [(size_t)NPTS * C];    // x lo plane
__device__ __half g_o1h[(size_t)NPTS * CH];   // out1 hi plane
__device__ __half g_o1l[(size_t)NPTS * CH];   // out1 lo plane
__device__ __half g_Wvh[C * CH], g_Wvl[C * CH];
__device__ __half g_Woh[CH * C], g_Wol[CH * C];
__device__ float g_P   [(size_t)NPTS * KK];   // x @ Wq^T
__device__ float g_q   [NPTS];                // raw q (pre-BN)
__device__ float g_y   [(size_t)NPTS * C];    // out1 @ Wout (pre-BN)
__device__ float g_part[NSB * 1024];          // column-stat partials
__device__ float g_qpart[2 * NSB];            // q stat partials
__device__ float g_vab [2 * CH];              // v BN affine (a, b)
__device__ float g_qab [2];                   // q BN affine
__device__ float g_yab [2 * C];               // y BN affine
__device__ float g_ksum[MM * KK];             // cb.sum(-1)
__device__ float g_choice[(size_t)NPTS * MM];

__device__ __forceinline__ void split2(float f, __half& hi, __half& lo) {
    hi = __float2half_rn(f);
    lo = __float2half_rn(f - __half2float(hi));
}

// ---------------- fp32 -> (hi, lo) fp16 planes --------------------------------
__global__ void __launch_bounds__(256) split_kernel(
    const float4* __restrict__ in, __half2* __restrict__ oh,
    __half2* __restrict__ ol, int n4)
{
    int i = blockIdx.x * 256 + threadIdx.x;
    if (i >= n4) return;
    float4 v = in[i];
    __half h0,l0,h1,l1,h2,l2,h3,l3;
    split2(v.x,h0,l0); split2(v.y,h1,l1); split2(v.z,h2,l2); split2(v.w,h3,l3);
    oh[2*i]   = __halves2half2(h0,h1); oh[2*i+1] = __halves2half2(h2,h3);
    ol[2*i]   = __halves2half2(l0,l1); ol[2*i+1] = __halves2half2(l2,l3);
}

// =====================================================================
// Pure-fp16 split GEMM, cp.async double-buffered.
// C[N,Ncols] = (Ah+Al)[N,Kd] @ (Bh+Bl)[Kd,Ncols], fp32 accum:
// D += Ah*Bh + Ah*Bl + Al*Bh. Tile 128x128x32, 256 thr (2x4 warps).
// =====================================================================
constexpr int APITCH = 40;   // halves; 80B rows -> conflict-free LDSM, 16B-mult
constexpr int BPITCH = 136;  // halves; 272B rows -> conflict-free LDSM, 16B-mult
constexpr int HG_SMEM = (2 * 2 * 128 * APITCH + 2 * 2 * 32 * BPITCH) * 2;

__device__ __forceinline__ void cpasync16(__half* dst, const __half* src) {
    unsigned d = (unsigned)__cvta_generic_to_shared(dst);
    asm volatile("cp.async.cg.shared.global [%0], [%1], 16;\n" :: "r"(d), "l"(src));
}

template<int Kd, bool HALF_OUT>
__global__ void __launch_bounds__(256) hgemm16(
    const __half* __restrict__ Ahg, const __half* __restrict__ Alg,
    const __half* __restrict__ Bhg, const __half* __restrict__ Blg,
    void* __restrict__ Cout, int Ncols)
{
    extern __shared__ float smraw[];
    __half* As = reinterpret_cast<__half*>(smraw);           // [2][2][128*APITCH]
    __half* Bs = As + 2 * 2 * 128 * APITCH;                  // [2][2][32*BPITCH]

    const int tid  = threadIdx.x;
    const int warp = tid >> 5, lane = tid & 31;
    const int wm = warp >> 2;       // 0..1
    const int wn = warp & 3;        // 0..3
    const int rowBase = blockIdx.x * 128;
    const int colBase = blockIdx.y * 128;
    constexpr int KT = Kd / 32;

    float acc[4][4][4];
#pragma unroll
    for (int i = 0; i < 4; i++)
#pragma unroll
        for (int j = 0; j < 4; j++)
#pragma unroll
            for (int f = 0; f < 4; f++) acc[i][j][f] = 0.f;

    auto load_stage = [&](int s, int k0) {
        __half* Ah_s = As + (s * 2 + 0) * (128 * APITCH);
        __half* Al_s = As + (s * 2 + 1) * (128 * APITCH);
        __half* Bh_s = Bs + (s * 2 + 0) * (32 * BPITCH);
        __half* Bl_s = Bs + (s * 2 + 1) * (32 * BPITCH);
#pragma unroll
        for (int it = 0; it < 2; it++) {
            int idx = it * 256 + tid;
            int r = idx >> 2, q = idx & 3;                    // A: 128 rows x 4 chunks
            size_t ga = (size_t)(rowBase + r) * Kd + k0 + q * 8;
            cpasync16(&Ah_s[r * APITCH + q * 8], &Ahg[ga]);
            cpasync16(&Al_s[r * APITCH + q * 8], &Alg[ga]);
            int rb = idx >> 4, qb = idx & 15;                 // B: 32 rows x 16 chunks
            size_t gb = (size_t)(k0 + rb) * Ncols + colBase + qb * 8;
            cpasync16(&Bh_s[rb * BPITCH + qb * 8], &Bhg[gb]);
            cpasync16(&Bl_s[rb * BPITCH + qb * 8], &Blg[gb]);
        }
        asm volatile("cp.async.commit_group;\n" ::);
    };

    load_stage(0, 0);

    for (int kt = 0; kt < KT; kt++) {
        if (kt + 1 < KT) {
            load_stage((kt + 1) & 1, (kt + 1) * 32);
            asm volatile("cp.async.wait_group 1;\n" ::);
        } else {
            asm volatile("cp.async.wait_group 0;\n" ::);
        }
        __syncthreads();

        const int s = kt & 1;
        const __half* Ah_s = As + (s * 2 + 0) * (128 * APITCH);
        const __half* Al_s = As + (s * 2 + 1) * (128 * APITCH);
        const __half* Bh_s = Bs + (s * 2 + 0) * (32 * BPITCH);
        const __half* Bl_s = Bs + (s * 2 + 1) * (32 * BPITCH);

#pragma unroll
        for (int ks = 0; ks < 32; ks += 16) {
            unsigned ah[4][4], al[4][4];
#pragma unroll
            for (int mt = 0; mt < 4; mt++) {
                int row = wm * 64 + mt * 16 + (lane & 15);
                int col = ks + (lane >> 4) * 8;
                unsigned aH = (unsigned)__cvta_generic_to_shared(&Ah_s[row * APITCH + col]);
                unsigned aL = (unsigned)__cvta_generic_to_shared(&Al_s[row * APITCH + col]);
                asm volatile("ldmatrix.sync.aligned.m8n8.x4.shared.b16 {%0,%1,%2,%3}, [%4];"
                    : "=r"(ah[mt][0]),"=r"(ah[mt][1]),"=r"(ah[mt][2]),"=r"(ah[mt][3]) : "r"(aH));
                asm volatile("ldmatrix.sync.aligned.m8n8.x4.shared.b16 {%0,%1,%2,%3}, [%4];"
                    : "=r"(al[mt][0]),"=r"(al[mt][1]),"=r"(al[mt][2]),"=r"(al[mt][3]) : "r"(aL));
            }
            unsigned bh[4][2], bl[4][2];
#pragma unroll
            for (int pr = 0; pr < 2; pr++) {
                int krow = ks + (lane & 15);
                int col = wn * 32 + pr * 16 + (lane >> 4) * 8;
                unsigned aH = (unsigned)__cvta_generic_to_shared(&Bh_s[krow * BPITCH + col]);
                unsigned aL = (unsigned)__cvta_generic_to_shared(&Bl_s[krow * BPITCH + col]);
                asm volatile("ldmatrix.sync.aligned.m8n8.x4.trans.shared.b16 {%0,%1,%2,%3}, [%4];"
                    : "=r"(bh[pr*2][0]),"=r"(bh[pr*2][1]),"=r"(bh[pr*2+1][0]),"=r"(bh[pr*2+1][1]) : "r"(aH));
                asm volatile("ldmatrix.sync.aligned.m8n8.x4.trans.shared.b16 {%0,%1,%2,%3}, [%4];"
                    : "=r"(bl[pr*2][0]),"=r"(bl[pr*2][1]),"=r"(bl[pr*2+1][0]),"=r"(bl[pr*2+1][1]) : "r"(aL));
            }
#pragma unroll
            for (int mt = 0; mt < 4; mt++)
#pragma unroll
                for (int nt = 0; nt < 4; nt++) {
                    float* d = acc[mt][nt];
#define MMA(Af, Bf) \
    asm volatile("mma.sync.aligned.m16n8k16.row.col.f32.f16.f16.f32 " \
        "{%0,%1,%2,%3}, {%4,%5,%6,%7}, {%8,%9}, {%0,%1,%2,%3};" \
        : "+f"(d[0]),"+f"(d[1]),"+f"(d[2]),"+f"(d[3]) \
        : "r"(Af[0]),"r"(Af[1]),"r"(Af[2]),"r"(Af[3]), "r"(Bf[0]),"r"(Bf[1]))
                    MMA(ah[mt], bh[nt]);
                    MMA(ah[mt], bl[nt]);
                    MMA(al[mt], bh[nt]);
#undef MMA
                }
        }
        __syncthreads();
    }

    const int g = lane >> 2, tg = lane & 3;
#pragma unroll
    for (int mt = 0; mt < 4; mt++)
#pragma unroll
        for (int nt = 0; nt < 4; nt++) {
            size_t row = (size_t)rowBase + wm * 64 + mt * 16 + g;
            int col = colBase + wn * 32 + nt * 8 + tg * 2;
            float* d = acc[mt][nt];
            if constexpr (HALF_OUT) {
                __half* Cm = (__half*)Cout;
                *reinterpret_cast<__half2*>(&Cm[row * Ncols + col]) =
                    __floats2half2_rn(d[0], d[1]);
                *reinterpret_cast<__half2*>(&Cm[(row + 8) * Ncols + col]) =
                    __floats2half2_rn(d[2], d[3]);
            } else {
                float* Cm = (float*)Cout;
                *reinterpret_cast<float2*>(&Cm[row * Ncols + col]) =
                    make_float2(d[0], d[1]);
                *reinterpret_cast<float2*>(&Cm[(row + 8) * Ncols + col]) =
                    make_float2(d[2], d[3]);
            }
        }
}

// ---------------- P = x @ Wq^T : one warp per row -----------------------------
__global__ void __launch_bounds__(256) p_gemm(
    const float* __restrict__ x, const float* __restrict__ Wq,
    float* __restrict__ P)
{
    __shared__ float wqs[KK * C];
    for (int i = threadIdx.x; i < KK * C; i += 256) wqs[i] = Wq[i];
    __syncthreads();
    const int warp = threadIdx.x >> 5, lane = threadIdx.x & 31;
    const int row = blockIdx.x * 8 + warp;
    float4 xv = reinterpret_cast<const float4*>(x + (size_t)row * C)[lane];
#pragma unroll
    for (int k = 0; k < KK; k++) {
        float4 w = reinterpret_cast<const float4*>(wqs + k * C)[lane];
        float d = xv.x * w.x + xv.y * w.y + xv.z * w.z + xv.w * w.w;
#pragma unroll
        for (int o = 16; o; o >>= 1) d += __shfl_xor_sync(0xFFFFFFFFu, d, o);
        if (lane == 0) P[(size_t)row * KK + k] = d;
    }
}

// ---------------- column stats (fp16 data) -------------------------------------
__global__ void colstats_half(const __half2* __restrict__ data, int rowsPerBlock,
                              float* __restrict__ part)
{
    const int r0 = blockIdx.x * rowsPerBlock;
    const int t = threadIdx.x;
    const int col = t & 127;
    const int rOff = t >> 7;
    float sl = 0.f, sl2 = 0.f, sh = 0.f, sh2 = 0.f;
    for (int r = r0 + rOff; r < r0 + rowsPerBlock; r += 2) {
        float2 v = __half22float2(data[(size_t)r * 128 + col]);
        sl += v.x; sl2 = fmaf(v.x, v.x, sl2);
        sh += v.y; sh2 = fmaf(v.y, v.y, sh2);
    }
    float* p = part + (size_t)blockIdx.x * 1024;
    p[t] = sl; p[256 + t] = sl2; p[512 + t] = sh; p[768 + t] = sh2;
}

__global__ void reduce_affine_v(const float* __restrict__ part,
    const float* __restrict__ gg, const float* __restrict__ bb,
    float* __restrict__ ab, float invN)
{
    const int c = blockIdx.x;
    const int m = c >> 1;
    const int offS = (c & 1) * 512;
    float s = 0.f, s2 = 0.f;
    for (int blk = threadIdx.x; blk < NSB; blk += 256) {
        const float* p = part + (size_t)blk * 1024;
        s  += p[offS + m] + p[offS + m + 128];
        s2 += p[offS + 256 + m] + p[offS + 256 + m + 128];
    }
    __shared__ float shm[512];
    shm[threadIdx.x] = s; shm[256 + threadIdx.x] = s2;
    __syncthreads();
    for (int o = 128; o; o >>= 1) {
        if (threadIdx.x < o) {
            shm[threadIdx.x] += shm[threadIdx.x + o];
            shm[256 + threadIdx.x] += shm[256 + threadIdx.x + o];
        }
        __syncthreads();
    }
    if (threadIdx.x == 0) {
        float mu  = shm[0] * invN;
        float var = fmaf(-mu, mu, shm[256] * invN);
        float a = gg[c] * rsqrtf(var + EPSV);
        ab[c] = a;
        ab[CH + c] = fmaf(-mu, a, bb[c]);
    }
}

__global__ void colstats_f32(const float* __restrict__ data, size_t perBlock,
                             float* __restrict__ part)
{
    size_t base = perBlock * blockIdx.x;
    float s = 0.f, s2 = 0.f;
    for (size_t i = base + threadIdx.x; i < base + perBlock; i += 256) {
        float v = data[i];
        s += v; s2 = fmaf(v, v, s2);
    }
    float* p = part + (size_t)blockIdx.x * 1024;
    p[threadIdx.x] = s;
    p[256 + threadIdx.x] = s2;
}

__global__ void reduce_affine_y(const float* __restrict__ part,
    const float* __restrict__ gg, const float* __restrict__ bb,
    float* __restrict__ ab, float invN)
{
    const int c = blockIdx.x;
    float s = 0.f, s2 = 0.f;
    for (int blk = threadIdx.x; blk < NSB; blk += 256) {
        const float* p = part + (size_t)blk * 1024;
        s  += p[c] + p[c + 128];
        s2 += p[256 + c] + p[256 + c + 128];
    }
    __shared__ float shm[512];
    shm[threadIdx.x] = s; shm[256 + threadIdx.x] = s2;
    __syncthreads();
    for (int o = 128; o; o >>= 1) {
        if (threadIdx.x < o) {
            shm[threadIdx.x] += shm[threadIdx.x + o];
            shm[256 + threadIdx.x] += shm[256 + threadIdx.x + o];
        }
        __syncthreads();
    }
    if (threadIdx.x == 0) {
        float mu  = shm[0] * invN;
        float var = fmaf(-mu, mu, shm[256] * invN);
        float a = gg[c] * rsqrtf(var + EPSV);
        ab[c] = a;
        ab[C + c] = fmaf(-mu, a, bb[c]);
    }
}

// ---------------- ksum[m,k] = sum_c cb[m,k,c] ---------------------------------
__global__ void ksum_kernel(const float* __restrict__ cb, float* __restrict__ ks)
{
    __shared__ float sh[256];
    int row = blockIdx.x;
    sh[threadIdx.x] = cb[(size_t)row * CH + threadIdx.x];
    __syncthreads();
    for (int o = 128; o; o >>= 1) {
        if (threadIdx.x < o) sh[threadIdx.x] += sh[threadIdx.x + o];
        __syncthreads();
    }
    if (threadIdx.x == 0) ks[row] = sh[0];
}

// ---------------- q[n] = sum_k P[nbr[n,k], k] + stats -------------------------
__global__ void q_gather(const int* __restrict__ nbr, const float* __restrict__ P,
                         float* __restrict__ q, float* __restrict__ qpart)
{
    const int n = blockIdx.x * 256 + threadIdx.x;
    float s = 0.f;
#pragma unroll
    for (int k = 0; k < KK; k++) {
        int idx = nbr[(size_t)n * KK + k];
        s += P[(size_t)idx * KK + k];
    }
    q[n] = s;
    __shared__ float sh[512];
    sh[threadIdx.x] = s;
    sh[256 + threadIdx.x] = s * s;
    __syncthreads();
    for (int o = 128; o; o >>= 1) {
        if (threadIdx.x < o) {
            sh[threadIdx.x] += sh[threadIdx.x + o];
            sh[256 + threadIdx.x] += sh[256 + threadIdx.x + o];
        }
        __syncthreads();
    }
    if (threadIdx.x == 0) {
        qpart[blockIdx.x] = sh[0];
        qpart[NSB + blockIdx.x] = sh[256];
    }
}

__global__ void q_finalize(const float* __restrict__ qpart,
    const float* __restrict__ gq, const float* __restrict__ bq,
    float* __restrict__ qab, float invN)
{
    __shared__ float sh[2 * NSB];
    sh[threadIdx.x] = qpart[threadIdx.x];
    sh[NSB + threadIdx.x] = qpart[NSB + threadIdx.x];
    __syncthreads();
    for (int o = NSB / 2; o; o >>= 1) {
        if (threadIdx.x < o) {
            sh[threadIdx.x] += sh[threadIdx.x + o];
            sh[NSB + threadIdx.x] += sh[NSB + threadIdx.x + o];
        }
        __syncthreads();
    }
    if (threadIdx.x == 0) {
        float mu  = sh[0] * invN;
        float var = fmaf(-mu, mu, sh[NSB] * invN);
        float a = gq[0] * rsqrtf(var + EPSV);
        qab[0] = a;
        qab[1] = fmaf(-mu, a, bq[0]);
    }
}

// ---------------- choice = softmax( relu(bn(q))[nbr] @ ksum^T ) ---------------
__global__ void choice_kernel(const int* __restrict__ nbr, const float* __restrict__ q,
    const float* __restrict__ qab, const float* __restrict__ ks,
    float* __restrict__ choice)
{
    __shared__ float sks[2 * KK];
    if (threadIdx.x < 2 * KK) sks[threadIdx.x] = ks[threadIdx.x];
    __syncthreads();
    const int n = blockIdx.x * 256 + threadIdx.x;
    const float a = qab[0], b = qab[1];
    float l0 = 0.f, l1 = 0.f;
#pragma unroll
    for (int k = 0; k < KK; k++) {
        int idx = nbr[(size_t)n * KK + k];
        float qq = fmaxf(fmaf(q[idx], a, b), 0.f);
        l0 = fmaf(qq, sks[k], l0);
        l1 = fmaf(qq, sks[KK + k], l1);
    }
    float m = fmaxf(l0, l1);
    float e0 = expf(l0 - m), e1 = expf(l1 - m);
    float inv = 1.f / (e0 + e1);
    choice[(size_t)n * 2]     = e0 * inv;
    choice[(size_t)n * 2 + 1] = e1 * inv;
}

// ---------------- routed gather: k-outer, rows in registers --------------------
constexpr int RG_ROWS = 32;
constexpr int RG_SMEM = (2 * KK * CH + CH + CH + 2 * RG_ROWS + KK * RG_ROWS) * 4;

__global__ void __launch_bounds__(256) routed_gather(
    const __half2* __restrict__ vh, const int* __restrict__ nbr,
    const float* __restrict__ choice, const float* __restrict__ cb,
    const float* __restrict__ vab,
    __half2* __restrict__ o1h, __half2* __restrict__ o1l)
{
    extern __shared__ float sm[];
    float* s_cb = sm;
    float* s_a  = s_cb + 2 * KK * CH;
    float* s_b  = s_a + CH;
    float* s_ch = s_b + CH;
    int*   s_idx = (int*)(s_ch + 2 * RG_ROWS);
    const int tid = threadIdx.x;
    const int grp = tid >> 7;        // each 128-thread group: 16 of 32 rows
    const int c2  = tid & 127;
    const int n0 = blockIdx.x * RG_ROWS;

    for (int i = tid; i < 2 * KK * CH; i += 256) s_cb[i] = cb[i];
    s_a[tid] = vab[tid];
    s_b[tid] = vab[CH + tid];
    for (int i = tid; i < 2 * RG_ROWS; i += 256) s_ch[i] = choice[(size_t)n0 * 2 + i];
    for (int i = tid; i < KK * RG_ROWS; i += 256) s_idx[i] = nbr[(size_t)n0 * KK + i];
    __syncthreads();

    const float2 aa = reinterpret_cast<const float2*>(s_a)[c2];
    const float2 bb = reinterpret_cast<const float2*>(s_b)[c2];
    const float2* cb2 = reinterpret_cast<const float2*>(s_cb);

    float acc[16][2];
#pragma unroll
    for (int r8 = 0; r8 < 16; r8++) { acc[r8][0] = 0.f; acc[r8][1] = 0.f; }

    for (int k = 0; k < KK; k++) {
        const float2 w0 = cb2[k * 128 + c2];
        const float2 w1 = cb2[(KK + k) * 128 + c2];
#pragma unroll
        for (int r8 = 0; r8 < 16; r8++) {
            const int r = r8 * 2 + grp;
            const int idx = s_idx[r * KK + k];
            const __half2 hv = __ldcg(&vh[(size_t)idx * 128 + c2]);
            const float2 vv = __half22float2(hv);
            const float v0 = fmaxf(fmaf(vv.x, aa.x, bb.x), 0.f);
            const float v1 = fmaxf(fmaf(vv.y, aa.y, bb.y), 0.f);
            const float c0 = s_ch[2 * r], c1 = s_ch[2 * r + 1];
            acc[r8][0] = fmaf(v0, fmaf(c1, w1.x, c0 * w0.x), acc[r8][0]);
            acc[r8][1] = fmaf(v1, fmaf(c1, w1.y, c0 * w0.y), acc[r8][1]);
        }
    }
#pragma unroll
    for (int r8 = 0; r8 < 16; r8++) {
        const int r = r8 * 2 + grp;
        const size_t row = (size_t)(n0 + r);
        __half h0, l0, h1, l1;
        split2(acc[r8][0], h0, l0);
        split2(acc[r8][1], h1, l1);
        o1h[row * 128 + c2] = __halves2half2(h0, h1);
        o1l[row * 128 + c2] = __halves2half2(l0, l1);
    }
}

// ---------------- final: relu(bn(y)) + x --------------------------------------
__global__ void final_kernel(const float* __restrict__ y, const float* __restrict__ x,
    const float* __restrict__ yab, float* __restrict__ out)
{
    const int i = blockIdx.x * 256 + threadIdx.x;
    const int ch = i & (C - 1);
    const float a = yab[ch], b = yab[C + ch];
    out[i] = fmaxf(fmaf(y[i], a, b), 0.f) + x[i];
}

// ---------------- launch -------------------------------------------------------
extern "C" void kernel_launch(void* const* d_in, const int* in_sizes, int n_in,
                              void* d_out, int out_size)
{
    const float* x    = (const float*)d_in[0];
    const int*   nbr  = (const int*)  d_in[1];
    const float* Wv   = (const float*)d_in[2];
    const float* gv   = (const float*)d_in[3];
    const float* bv   = (const float*)d_in[4];
    const float* Wq   = (const float*)d_in[5];
    const float* gq   = (const float*)d_in[6];
    const float* bq   = (const float*)d_in[7];
    const float* cb   = (const float*)d_in[8];
    const float* Wout = (const float*)d_in[9];
    const float* go   = (const float*)d_in[10];
    const float* bo   = (const float*)d_in[11];
    float* out = (float*)d_out;
    const int N = in_sizes[0] / C;

    __half *pvh, *pxh, *pxl, *po1h, *po1l, *pWvh, *pWvl, *pWoh, *pWol;
    float *pP, *pq, *py, *ppart, *pqpart, *pvab, *pqab, *pyab, *pksum, *pchoice;
    cudaGetSymbolAddress((void**)&pvh,    g_vh);
    cudaGetSymbolAddress((void**)&pxh,    g_xh);
    cudaGetSymbolAddress((void**)&pxl,    g_xl);
    cudaGetSymbolAddress((void**)&po1h,   g_o1h);
    cudaGetSymbolAddress((void**)&po1l,   g_o1l);
    cudaGetSymbolAddress((void**)&pWvh,   g_Wvh);
    cudaGetSymbolAddress((void**)&pWvl,   g_Wvl);
    cudaGetSymbolAddress((void**)&pWoh,   g_Woh);
    cudaGetSymbolAddress((void**)&pWol,   g_Wol);
    cudaGetSymbolAddress((void**)&pP,     g_P);
    cudaGetSymbolAddress((void**)&pq,     g_q);
    cudaGetSymbolAddress((void**)&py,     g_y);
    cudaGetSymbolAddress((void**)&ppart,  g_part);
    cudaGetSymbolAddress((void**)&pqpart, g_qpart);
    cudaGetSymbolAddress((void**)&pvab,   g_vab);
    cudaGetSymbolAddress((void**)&pqab,   g_qab);
    cudaGetSymbolAddress((void**)&pyab,   g_yab);
    cudaGetSymbolAddress((void**)&pksum,  g_ksum);
    cudaGetSymbolAddress((void**)&pchoice,g_choice);

    cudaFuncSetAttribute(routed_gather,
                         cudaFuncAttributeMaxDynamicSharedMemorySize, RG_SMEM);
    cudaFuncSetAttribute(hgemm16<128, true>,
                         cudaFuncAttributeMaxDynamicSharedMemorySize, HG_SMEM);
    cudaFuncSetAttribute(hgemm16<256, false>,
                         cudaFuncAttributeMaxDynamicSharedMemorySize, HG_SMEM);

    const float invN = 1.f / (float)N;

    // pre-split x and weights into fp16 hi/lo planes
    split_kernel<<<(N * C / 4 + 255) / 256, 256>>>(
        (const float4*)x, (__half2*)pxh, (__half2*)pxl, N * C / 4);
    split_kernel<<<(C * CH / 4 + 255) / 256, 256>>>(
        (const float4*)Wv, (__half2*)pWvh, (__half2*)pWvl, C * CH / 4);
    split_kernel<<<(CH * C / 4 + 255) / 256, 256>>>(
        (const float4*)Wout, (__half2*)pWoh, (__half2*)pWol, CH * C / 4);

    // v = x @ Wv  (pipelined fp16 split GEMM, fp16 out)
    hgemm16<128, true><<<dim3(N / 128, CH / 128), 256, HG_SMEM>>>(
        pxh, pxl, pWvh, pWvl, pvh, CH);
    // P = x @ Wq^T
    p_gemm<<<N / 8, 256>>>(x, Wq, pP);
    // v BN stats -> affine
    colstats_half<<<NSB, 256>>>((const __half2*)pvh, N / NSB, ppart);
    reduce_affine_v<<<CH, 256>>>(ppart, gv, bv, pvab, invN);
    // ksum from codebook
    ksum_kernel<<<MM * KK, 256>>>(cb, pksum);
    // q = gather-sum of P, with stats
    q_gather<<<N / 256, 256>>>(nbr, pP, pq, pqpart);
    q_finalize<<<1, NSB>>>(pqpart, gq, bq, pqab, invN);
    // routing weights
    choice_kernel<<<N / 256, 256>>>(nbr, pq, pqab, pksum, pchoice);
    // routed channelwise gather conv -> hi/lo fp16 planes
    routed_gather<<<N / RG_ROWS, 256, RG_SMEM>>>(
        (const __half2*)pvh, nbr, pchoice, cb, pvab,
        (__half2*)po1h, (__half2*)po1l);
    // y = out1 @ Wout (pipelined fp16 split GEMM, fp32 out)
    hgemm16<256, false><<<dim3(N / 128, 1), 256, HG_SMEM>>>(
        po1h, po1l, pWoh, pWol, py, C);
    // y BN stats -> affine
    colstats_f32<<<NSB, 256>>>(py, (size_t)N * C / NSB, ppart);
    reduce_affine_y<<<C, 256>>>(ppart, go, bo, pyab, invN);
    // out = relu(bn(y)) + x
    final_kernel<<<(size_t)N * C / 256, 256>>>(py, x, pyab, out);
}

// round 6
// speedup vs baseline: 2.5039x; 1.2655x over previous
#include <cuda_runtime.h>
#include <cuda_fp16.h>
#include <math.h>

#define EPSV 1e-5f

constexpr int C   = 128;
constexpr int CH  = 256;   // C*H
constexpr int KK  = 27;
constexpr int MM  = 2;
constexpr int NPTS = 131072;
constexpr int NSB = 512;   // stat partial blocks

// ---------------- device scratch (static; no allocations allowed) --------------
__device__ __half g_vh [(size_t)NPTS * CH];   // x @ Wv (pre-BN), fp16
__device__ __half g_vr [(size_t)NPTS * CH];   // relu(bn(v)), fp16
__device__ __half g_xh [(size_t)NPTS * C];    // x hi plane
__device__ __half g_xl [(size_t)NPTS * C];    // x lo plane
__device__ __half g_o1h[(size_t)NPTS * CH];   // out1 hi plane
__device__ __half g_o1l[(size_t)NPTS * CH];   // out1 lo plane
__device__ __half g_Wvh[C * CH], g_Wvl[C * CH];
__device__ __half g_Woh[CH * C], g_Wol[CH * C];
__device__ float g_P   [(size_t)NPTS * KK];   // x @ Wq^T
__device__ float g_q   [NPTS];                // raw q (pre-BN)
__device__ float g_y   [(size_t)NPTS * C];    // out1 @ Wout (pre-BN)
__device__ float g_part[NSB * 1024];          // column-stat partials
__device__ float g_qpart[2 * NSB];            // q stat partials
__device__ float g_vab [2 * CH];              // v BN affine (a, b)
__device__ float g_qab [2];                   // q BN affine
__device__ float g_yab [2 * C];               // y BN affine
__device__ float g_ksum[MM * KK];             // cb.sum(-1)
__device__ float g_choice[(size_t)NPTS * MM];

__device__ __forceinline__ void split2(float f, __half& hi, __half& lo) {
    hi = __float2half_rn(f);
    lo = __float2half_rn(f - __half2float(hi));
}

// ---------------- fp32 -> (hi, lo) fp16 planes --------------------------------
__global__ void __launch_bounds__(256) split_kernel(
    const float4* __restrict__ in, __half2* __restrict__ oh,
    __half2* __restrict__ ol, int n4)
{
    int i = blockIdx.x * 256 + threadIdx.x;
    if (i >= n4) return;
    float4 v = in[i];
    __half h0,l0,h1,l1,h2,l2,h3,l3;
    split2(v.x,h0,l0); split2(v.y,h1,l1); split2(v.z,h2,l2); split2(v.w,h3,l3);
    oh[2*i]   = __halves2half2(h0,h1); oh[2*i+1] = __halves2half2(h2,h3);
    ol[2*i]   = __halves2half2(l0,l1); ol[2*i+1] = __halves2half2(l2,l3);
}

// =====================================================================
// Pure-fp16 split GEMM, cp.async double-buffered
// =====================================================================
constexpr int APITCH = 40;
constexpr int BPITCH = 136;
constexpr int HG_SMEM = (2 * 2 * 128 * APITCH + 2 * 2 * 32 * BPITCH) * 2;

__device__ __forceinline__ void cpasync16(__half* dst, const __half* src) {
    unsigned d = (unsigned)__cvta_generic_to_shared(dst);
    asm volatile("cp.async.cg.shared.global [%0], [%1], 16;\n" :: "r"(d), "l"(src));
}

template<int Kd, bool HALF_OUT>
__global__ void __launch_bounds__(256) hgemm16(
    const __half* __restrict__ Ahg, const __half* __restrict__ Alg,
    const __half* __restrict__ Bhg, const __half* __restrict__ Blg,
    void* __restrict__ Cout, int Ncols)
{
    extern __shared__ float smraw[];
    __half* As = reinterpret_cast<__half*>(smraw);
    __half* Bs = As + 2 * 2 * 128 * APITCH;

    const int tid  = threadIdx.x;
    const int warp = tid >> 5, lane = tid & 31;
    const int wm = warp >> 2;
    const int wn = warp & 3;
    const int rowBase = blockIdx.x * 128;
    const int colBase = blockIdx.y * 128;
    constexpr int KT = Kd / 32;

    float acc[4][4][4];
#pragma unroll
    for (int i = 0; i < 4; i++)
#pragma unroll
        for (int j = 0; j < 4; j++)
#pragma unroll
            for (int f = 0; f < 4; f++) acc[i][j][f] = 0.f;

    auto load_stage = [&](int s, int k0) {
        __half* Ah_s = As + (s * 2 + 0) * (128 * APITCH);
        __half* Al_s = As + (s * 2 + 1) * (128 * APITCH);
        __half* Bh_s = Bs + (s * 2 + 0) * (32 * BPITCH);
        __half* Bl_s = Bs + (s * 2 + 1) * (32 * BPITCH);
#pragma unroll
        for (int it = 0; it < 2; it++) {
            int idx = it * 256 + tid;
            int r = idx >> 2, q = idx & 3;
            size_t ga = (size_t)(rowBase + r) * Kd + k0 + q * 8;
            cpasync16(&Ah_s[r * APITCH + q * 8], &Ahg[ga]);
            cpasync16(&Al_s[r * APITCH + q * 8], &Alg[ga]);
            int rb = idx >> 4, qb = idx & 15;
            size_t gb = (size_t)(k0 + rb) * Ncols + colBase + qb * 8;
            cpasync16(&Bh_s[rb * BPITCH + qb * 8], &Bhg[gb]);
            cpasync16(&Bl_s[rb * BPITCH + qb * 8], &Blg[gb]);
        }
        asm volatile("cp.async.commit_group;\n" ::);
    };

    load_stage(0, 0);

    for (int kt = 0; kt < KT; kt++) {
        if (kt + 1 < KT) {
            load_stage((kt + 1) & 1, (kt + 1) * 32);
            asm volatile("cp.async.wait_group 1;\n" ::);
        } else {
            asm volatile("cp.async.wait_group 0;\n" ::);
        }
        __syncthreads();

        const int s = kt & 1;
        const __half* Ah_s = As + (s * 2 + 0) * (128 * APITCH);
        const __half* Al_s = As + (s * 2 + 1) * (128 * APITCH);
        const __half* Bh_s = Bs + (s * 2 + 0) * (32 * BPITCH);
        const __half* Bl_s = Bs + (s * 2 + 1) * (32 * BPITCH);

#pragma unroll
        for (int ks = 0; ks < 32; ks += 16) {
            unsigned ah[4][4], al[4][4];
#pragma unroll
            for (int mt = 0; mt < 4; mt++) {
                int row = wm * 64 + mt * 16 + (lane & 15);
                int col = ks + (lane >> 4) * 8;
                unsigned aH = (unsigned)__cvta_generic_to_shared(&Ah_s[row * APITCH + col]);
                unsigned aL = (unsigned)__cvta_generic_to_shared(&Al_s[row * APITCH + col]);
                asm volatile("ldmatrix.sync.aligned.m8n8.x4.shared.b16 {%0,%1,%2,%3}, [%4];"
                    : "=r"(ah[mt][0]),"=r"(ah[mt][1]),"=r"(ah[mt][2]),"=r"(ah[mt][3]) : "r"(aH));
                asm volatile("ldmatrix.sync.aligned.m8n8.x4.shared.b16 {%0,%1,%2,%3}, [%4];"
                    : "=r"(al[mt][0]),"=r"(al[mt][1]),"=r"(al[mt][2]),"=r"(al[mt][3]) : "r"(aL));
            }
            unsigned bh[4][2], bl[4][2];
#pragma unroll
            for (int pr = 0; pr < 2; pr++) {
                int krow = ks + (lane & 15);
                int col = wn * 32 + pr * 16 + (lane >> 4) * 8;
                unsigned aH = (unsigned)__cvta_generic_to_shared(&Bh_s[krow * BPITCH + col]);
                unsigned aL = (unsigned)__cvta_generic_to_shared(&Bl_s[krow * BPITCH + col]);
                asm volatile("ldmatrix.sync.aligned.m8n8.x4.trans.shared.b16 {%0,%1,%2,%3}, [%4];"
                    : "=r"(bh[pr*2][0]),"=r"(bh[pr*2][1]),"=r"(bh[pr*2+1][0]),"=r"(bh[pr*2+1][1]) : "r"(aH));
                asm volatile("ldmatrix.sync.aligned.m8n8.x4.trans.shared.b16 {%0,%1,%2,%3}, [%4];"
                    : "=r"(bl[pr*2][0]),"=r"(bl[pr*2][1]),"=r"(bl[pr*2+1][0]),"=r"(bl[pr*2+1][1]) : "r"(aL));
            }
#pragma unroll
            for (int mt = 0; mt < 4; mt++)
#pragma unroll
                for (int nt = 0; nt < 4; nt++) {
                    float* d = acc[mt][nt];
#define MMA(Af, Bf) \
    asm volatile("mma.sync.aligned.m16n8k16.row.col.f32.f16.f16.f32 " \
        "{%0,%1,%2,%3}, {%4,%5,%6,%7}, {%8,%9}, {%0,%1,%2,%3};" \
        : "+f"(d[0]),"+f"(d[1]),"+f"(d[2]),"+f"(d[3]) \
        : "r"(Af[0]),"r"(Af[1]),"r"(Af[2]),"r"(Af[3]), "r"(Bf[0]),"r"(Bf[1]))
                    MMA(ah[mt], bh[nt]);
                    MMA(ah[mt], bl[nt]);
                    MMA(al[mt], bh[nt]);
#undef MMA
                }
        }
        __syncthreads();
    }

    const int g = lane >> 2, tg = lane & 3;
#pragma unroll
    for (int mt = 0; mt < 4; mt++)
#pragma unroll
        for (int nt = 0; nt < 4; nt++) {
            size_t row = (size_t)rowBase + wm * 64 + mt * 16 + g;
            int col = colBase + wn * 32 + nt * 8 + tg * 2;
            float* d = acc[mt][nt];
            if constexpr (HALF_OUT) {
                __half* Cm = (__half*)Cout;
                *reinterpret_cast<__half2*>(&Cm[row * Ncols + col]) =
                    __floats2half2_rn(d[0], d[1]);
                *reinterpret_cast<__half2*>(&Cm[(row + 8) * Ncols + col]) =
                    __floats2half2_rn(d[2], d[3]);
            } else {
                float* Cm = (float*)Cout;
                *reinterpret_cast<float2*>(&Cm[row * Ncols + col]) =
                    make_float2(d[0], d[1]);
                *reinterpret_cast<float2*>(&Cm[(row + 8) * Ncols + col]) =
                    make_float2(d[2], d[3]);
            }
        }
}

// ---------------- P = x @ Wq^T : register partials + smem transpose reduce -----
__global__ void __launch_bounds__(256) p_gemm(
    const float* __restrict__ x, const float* __restrict__ Wq,
    float* __restrict__ P)
{
    __shared__ float wqs[KK * C];
    __shared__ float red[8][KK * 32];
    for (int i = threadIdx.x; i < KK * C; i += 256) wqs[i] = Wq[i];
    __syncthreads();
    const int warp = threadIdx.x >> 5, lane = threadIdx.x & 31;
    const int row = blockIdx.x * 8 + warp;
    float4 xv = reinterpret_cast<const float4*>(x + (size_t)row * C)[lane];
    float part[KK];
#pragma unroll
    for (int k = 0; k < KK; k++) {
        float4 w = reinterpret_cast<const float4*>(wqs + k * C)[lane];
        part[k] = xv.x * w.x + xv.y * w.y + xv.z * w.z + xv.w * w.w;
    }
#pragma unroll
    for (int k = 0; k < KK; k++) red[warp][lane * KK + k] = part[k];
    __syncwarp();
    if (lane < KK) {
        float s = 0.f;
#pragma unroll
        for (int j = 0; j < 32; j++) s += red[warp][j * KK + lane];
        P[(size_t)row * KK + lane] = s;
    }
}

// ---------------- column stats (fp16 data) -------------------------------------
__global__ void colstats_half(const __half2* __restrict__ data, int rowsPerBlock,
                              float* __restrict__ part)
{
    const int r0 = blockIdx.x * rowsPerBlock;
    const int t = threadIdx.x;
    const int col = t & 127;
    const int rOff = t >> 7;
    float sl = 0.f, sl2 = 0.f, sh = 0.f, sh2 = 0.f;
    for (int r = r0 + rOff; r < r0 + rowsPerBlock; r += 2) {
        float2 v = __half22float2(data[(size_t)r * 128 + col]);
        sl += v.x; sl2 = fmaf(v.x, v.x, sl2);
        sh += v.y; sh2 = fmaf(v.y, v.y, sh2);
    }
    float* p = part + (size_t)blockIdx.x * 1024;
    p[t] = sl; p[256 + t] = sl2; p[512 + t] = sh; p[768 + t] = sh2;
}

__global__ void reduce_affine_v(const float* __restrict__ part,
    const float* __restrict__ gg, const float* __restrict__ bb,
    float* __restrict__ ab, float invN)
{
    const int c = blockIdx.x;
    const int m = c >> 1;
    const int offS = (c & 1) * 512;
    float s = 0.f, s2 = 0.f;
    for (int blk = threadIdx.x; blk < NSB; blk += 256) {
        const float* p = part + (size_t)blk * 1024;
        s  += p[offS + m] + p[offS + m + 128];
        s2 += p[offS + 256 + m] + p[offS + 256 + m + 128];
    }
    __shared__ float shm[512];
    shm[threadIdx.x] = s; shm[256 + threadIdx.x] = s2;
    __syncthreads();
    for (int o = 128; o; o >>= 1) {
        if (threadIdx.x < o) {
            shm[threadIdx.x] += shm[threadIdx.x + o];
            shm[256 + threadIdx.x] += shm[256 + threadIdx.x + o];
        }
        __syncthreads();
    }
    if (threadIdx.x == 0) {
        float mu  = shm[0] * invN;
        float var = fmaf(-mu, mu, shm[256] * invN);
        float a = gg[c] * rsqrtf(var + EPSV);
        ab[c] = a;
        ab[CH + c] = fmaf(-mu, a, bb[c]);
    }
}

// ---------------- vr = relu(bn(v)) as fp16 -------------------------------------
__global__ void __launch_bounds__(256) vrelu_kernel(
    const __half2* __restrict__ vh, const float* __restrict__ vab,
    __half2* __restrict__ vr, int n2)
{
    int i = blockIdx.x * 256 + threadIdx.x;
    if (i >= n2) return;
    int c2 = i & 127;
    float2 a = reinterpret_cast<const float2*>(vab)[c2];
    float2 b = reinterpret_cast<const float2*>(vab + CH)[c2];
    float2 v = __half22float2(vh[i]);
    vr[i] = __floats2half2_rn(fmaxf(fmaf(v.x, a.x, b.x), 0.f),
                              fmaxf(fmaf(v.y, a.y, b.y), 0.f));
}

__global__ void colstats_f32(const float* __restrict__ data, size_t perBlock,
                             float* __restrict__ part)
{
    size_t base = perBlock * blockIdx.x;
    float s = 0.f, s2 = 0.f;
    for (size_t i = base + threadIdx.x; i < base + perBlock; i += 256) {
        float v = data[i];
        s += v; s2 = fmaf(v, v, s2);
    }
    float* p = part + (size_t)blockIdx.x * 1024;
    p[threadIdx.x] = s;
    p[256 + threadIdx.x] = s2;
}

__global__ void reduce_affine_y(const float* __restrict__ part,
    const float* __restrict__ gg, const float* __restrict__ bb,
    float* __restrict__ ab, float invN)
{
    const int c = blockIdx.x;
    float s = 0.f, s2 = 0.f;
    for (int blk = threadIdx.x; blk < NSB; blk += 256) {
        const float* p = part + (size_t)blk * 1024;
        s  += p[c] + p[c + 128];
        s2 += p[256 + c] + p[256 + c + 128];
    }
    __shared__ float shm[512];
    shm[threadIdx.x] = s; shm[256 + threadIdx.x] = s2;
    __syncthreads();
    for (int o = 128; o; o >>= 1) {
        if (threadIdx.x < o) {
            shm[threadIdx.x] += shm[threadIdx.x + o];
            shm[256 + threadIdx.x] += shm[256 + threadIdx.x + o];
        }
        __syncthreads();
    }
    if (threadIdx.x == 0) {
        float mu  = shm[0] * invN;
        float var = fmaf(-mu, mu, shm[256] * invN);
        float a = gg[c] * rsqrtf(var + EPSV);
        ab[c] = a;
        ab[C + c] = fmaf(-mu, a, bb[c]);
    }
}

// ---------------- ksum[m,k] = sum_c cb[m,k,c] ---------------------------------
__global__ void ksum_kernel(const float* __restrict__ cb, float* __restrict__ ks)
{
    __shared__ float sh[256];
    int row = blockIdx.x;
    sh[threadIdx.x] = cb[(size_t)row * CH + threadIdx.x];
    __syncthreads();
    for (int o = 128; o; o >>= 1) {
        if (threadIdx.x < o) sh[threadIdx.x] += sh[threadIdx.x + o];
        __syncthreads();
    }
    if (threadIdx.x == 0) ks[row] = sh[0];
}

// ---------------- q[n] = sum_k P[nbr[n,k], k] + stats -------------------------
__global__ void q_gather(const int* __restrict__ nbr, const float* __restrict__ P,
                         float* __restrict__ q, float* __restrict__ qpart)
{
    const int n = blockIdx.x * 256 + threadIdx.x;
    float s = 0.f;
#pragma unroll
    for (int k = 0; k < KK; k++) {
        int idx = nbr[(size_t)n * KK + k];
        s += P[(size_t)idx * KK + k];
    }
    q[n] = s;
    __shared__ float sh[512];
    sh[threadIdx.x] = s;
    sh[256 + threadIdx.x] = s * s;
    __syncthreads();
    for (int o = 128; o; o >>= 1) {
        if (threadIdx.x < o) {
            sh[threadIdx.x] += sh[threadIdx.x + o];
            sh[256 + threadIdx.x] += sh[256 + threadIdx.x + o];
        }
        __syncthreads();
    }
    if (threadIdx.x == 0) {
        qpart[blockIdx.x] = sh[0];
        qpart[NSB + blockIdx.x] = sh[256];
    }
}

__global__ void q_finalize(const float* __restrict__ qpart,
    const float* __restrict__ gq, const float* __restrict__ bq,
    float* __restrict__ qab, float invN)
{
    __shared__ float sh[2 * NSB];
    sh[threadIdx.x] = qpart[threadIdx.x];
    sh[NSB + threadIdx.x] = qpart[NSB + threadIdx.x];
    __syncthreads();
    for (int o = NSB / 2; o; o >>= 1) {
        if (threadIdx.x < o) {
            sh[threadIdx.x] += sh[threadIdx.x + o];
            sh[NSB + threadIdx.x] += sh[NSB + threadIdx.x + o];
        }
        __syncthreads();
    }
    if (threadIdx.x == 0) {
        float mu  = sh[0] * invN;
        float var = fmaf(-mu, mu, sh[NSB] * invN);
        float a = gq[0] * rsqrtf(var + EPSV);
        qab[0] = a;
        qab[1] = fmaf(-mu, a, bq[0]);
    }
}

// ---------------- choice = softmax( relu(bn(q))[nbr] @ ksum^T ) ---------------
__global__ void choice_kernel(const int* __restrict__ nbr, const float* __restrict__ q,
    const float* __restrict__ qab, const float* __restrict__ ks,
    float* __restrict__ choice)
{
    __shared__ float sks[2 * KK];
    if (threadIdx.x < 2 * KK) sks[threadIdx.x] = ks[threadIdx.x];
    __syncthreads();
    const int n = blockIdx.x * 256 + threadIdx.x;
    const float a = qab[0], b = qab[1];
    float l0 = 0.f, l1 = 0.f;
#pragma unroll
    for (int k = 0; k < KK; k++) {
        int idx = nbr[(size_t)n * KK + k];
        float qq = fmaxf(fmaf(q[idx], a, b), 0.f);
        l0 = fmaf(qq, sks[k], l0);
        l1 = fmaf(qq, sks[KK + k], l1);
    }
    float m = fmaxf(l0, l1);
    float e0 = expf(l0 - m), e1 = expf(l1 - m);
    float inv = 1.f / (e0 + e1);
    choice[(size_t)n * 2]     = e0 * inv;
    choice[(size_t)n * 2 + 1] = e1 * inv;
}

// ---------------- routed gather: dual-acc, pre-BN'd v, 8B loads ----------------
constexpr int RG_ROWS = 16;
constexpr int RG_SMEM = (2 * KK * CH + 2 * RG_ROWS + KK * RG_ROWS) * 4;

__global__ void __launch_bounds__(256) routed_gather(
    const __half2* __restrict__ vr, const int* __restrict__ nbr,
    const float* __restrict__ choice, const float* __restrict__ cb,
    __half2* __restrict__ o1h, __half2* __restrict__ o1l)
{
    extern __shared__ float sm[];
    float* s_cb = sm;                           // 2*27*256
    float* s_ch = s_cb + 2 * KK * CH;           // 2*16
    int*   s_idx = (int*)(s_ch + 2 * RG_ROWS);  // 27*16
    const int tid = threadIdx.x;
    const int grp = tid >> 6;        // 0..3 -> rows j*4+grp
    const int c4  = tid & 63;        // channel quad: channels [c4*4, c4*4+4)
    const int n0 = blockIdx.x * RG_ROWS;

    for (int i = tid; i < 2 * KK * CH; i += 256) s_cb[i] = cb[i];
    if (tid < 2 * RG_ROWS) s_ch[tid] = choice[(size_t)n0 * 2 + tid];
    for (int i = tid; i < KK * RG_ROWS; i += 256) s_idx[i] = nbr[(size_t)n0 * KK + i];
    __syncthreads();

    float4 acc0[4], acc1[4];
#pragma unroll
    for (int j = 0; j < 4; j++) {
        acc0[j] = make_float4(0.f, 0.f, 0.f, 0.f);
        acc1[j] = make_float4(0.f, 0.f, 0.f, 0.f);
    }

    for (int k = 0; k < KK; k++) {
        const float4 w0 = reinterpret_cast<const float4*>(s_cb + k * CH)[c4];
        const float4 w1 = reinterpret_cast<const float4*>(s_cb + (KK + k) * CH)[c4];
#pragma unroll
        for (int j = 0; j < 4; j++) {
            const int r = j * 4 + grp;
            const int idx = s_idx[r * KK + k];
            const int2 raw = __ldcg(reinterpret_cast<const int2*>(
                vr + (size_t)idx * 128 + c4 * 2));
            const float2 va = __half22float2(*reinterpret_cast<const __half2*>(&raw.x));
            const float2 vb = __half22float2(*reinterpret_cast<const __half2*>(&raw.y));
            acc0[j].x = fmaf(va.x, w0.x, acc0[j].x);
            acc0[j].y = fmaf(va.y, w0.y, acc0[j].y);
            acc0[j].z = fmaf(vb.x, w0.z, acc0[j].z);
            acc0[j].w = fmaf(vb.y, w0.w, acc0[j].w);
            acc1[j].x = fmaf(va.x, w1.x, acc1[j].x);
            acc1[j].y = fmaf(va.y, w1.y, acc1[j].y);
            acc1[j].z = fmaf(vb.x, w1.z, acc1[j].z);
            acc1[j].w = fmaf(vb.y, w1.w, acc1[j].w);
        }
    }
#pragma unroll
    for (int j = 0; j < 4; j++) {
        const int r = j * 4 + grp;
        const float c0 = s_ch[2 * r], c1 = s_ch[2 * r + 1];
        float o0 = fmaf(c0, acc0[j].x, c1 * acc1[j].x);
        float o1 = fmaf(c0, acc0[j].y, c1 * acc1[j].y);
        float o2 = fmaf(c0, acc0[j].z, c1 * acc1[j].z);
        float o3 = fmaf(c0, acc0[j].w, c1 * acc1[j].w);
        __half h0,l0,h1,l1,h2,l2,h3,l3;
        split2(o0,h0,l0); split2(o1,h1,l1); split2(o2,h2,l2); split2(o3,h3,l3);
        const size_t base = (size_t)(n0 + r) * 128 + c4 * 2;
        o1h[base]     = __halves2half2(h0, h1);
        o1h[base + 1] = __halves2half2(h2, h3);
        o1l[base]     = __halves2half2(l0, l1);
        o1l[base + 1] = __halves2half2(l2, l3);
    }
}

// ---------------- final: relu(bn(y)) + x --------------------------------------
__global__ void final_kernel(const float* __restrict__ y, const float* __restrict__ x,
    const float* __restrict__ yab, float* __restrict__ out)
{
    const int i = blockIdx.x * 256 + threadIdx.x;
    const int ch = i & (C - 1);
    const float a = yab[ch], b = yab[C + ch];
    out[i] = fmaxf(fmaf(y[i], a, b), 0.f) + x[i];
}

// ---------------- launch -------------------------------------------------------
extern "C" void kernel_launch(void* const* d_in, const int* in_sizes, int n_in,
                              void* d_out, int out_size)
{
    const float* x    = (const float*)d_in[0];
    const int*   nbr  = (const int*)  d_in[1];
    const float* Wv   = (const float*)d_in[2];
    const float* gv   = (const float*)d_in[3];
    const float* bv   = (const float*)d_in[4];
    const float* Wq   = (const float*)d_in[5];
    const float* gq   = (const float*)d_in[6];
    const float* bq   = (const float*)d_in[7];
    const float* cb   = (const float*)d_in[8];
    const float* Wout = (const float*)d_in[9];
    const float* go   = (const float*)d_in[10];
    const float* bo   = (const float*)d_in[11];
    float* out = (float*)d_out;
    const int N = in_sizes[0] / C;

    __half *pvh, *pvr, *pxh, *pxl, *po1h, *po1l, *pWvh, *pWvl, *pWoh, *pWol;
    float *pP, *pq, *py, *ppart, *pqpart, *pvab, *pqab, *pyab, *pksum, *pchoice;
    cudaGetSymbolAddress((void**)&pvh,    g_vh);
    cudaGetSymbolAddress((void**)&pvr,    g_vr);
    cudaGetSymbolAddress((void**)&pxh,    g_xh);
    cudaGetSymbolAddress((void**)&pxl,    g_xl);
    cudaGetSymbolAddress((void**)&po1h,   g_o1h);
    cudaGetSymbolAddress((void**)&po1l,   g_o1l);
    cudaGetSymbolAddress((void**)&pWvh,   g_Wvh);
    cudaGetSymbolAddress((void**)&pWvl,   g_Wvl);
    cudaGetSymbolAddress((void**)&pWoh,   g_Woh);
    cudaGetSymbolAddress((void**)&pWol,   g_Wol);
    cudaGetSymbolAddress((void**)&pP,     g_P);
    cudaGetSymbolAddress((void**)&pq,     g_q);
    cudaGetSymbolAddress((void**)&py,     g_y);
    cudaGetSymbolAddress((void**)&ppart,  g_part);
    cudaGetSymbolAddress((void**)&pqpart, g_qpart);
    cudaGetSymbolAddress((void**)&pvab,   g_vab);
    cudaGetSymbolAddress((void**)&pqab,   g_qab);
    cudaGetSymbolAddress((void**)&pyab,   g_yab);
    cudaGetSymbolAddress((void**)&pksum,  g_ksum);
    cudaGetSymbolAddress((void**)&pchoice,g_choice);

    cudaFuncSetAttribute(routed_gather,
                         cudaFuncAttributeMaxDynamicSharedMemorySize, RG_SMEM);
    cudaFuncSetAttribute(hgemm16<128, true>,
                         cudaFuncAttributeMaxDynamicSharedMemorySize, HG_SMEM);
    cudaFuncSetAttribute(hgemm16<256, false>,
                         cudaFuncAttributeMaxDynamicSharedMemorySize, HG_SMEM);

    const float invN = 1.f / (float)N;

    // pre-split x and weights into fp16 hi/lo planes
    split_kernel<<<(N * C / 4 + 255) / 256, 256>>>(
        (const float4*)x, (__half2*)pxh, (__half2*)pxl, N * C / 4);
    split_kernel<<<(C * CH / 4 + 255) / 256, 256>>>(
        (const float4*)Wv, (__half2*)pWvh, (__half2*)pWvl, C * CH / 4);
    split_kernel<<<(CH * C / 4 + 255) / 256, 256>>>(
        (const float4*)Wout, (__half2*)pWoh, (__half2*)pWol, CH * C / 4);

    // v = x @ Wv  (pipelined fp16 split GEMM, fp16 out)
    hgemm16<128, true><<<dim3(N / 128, CH / 128), 256, HG_SMEM>>>(
        pxh, pxl, pWvh, pWvl, pvh, CH);
    // P = x @ Wq^T
    p_gemm<<<N / 8, 256>>>(x, Wq, pP);
    // v BN stats -> affine
    colstats_half<<<NSB, 256>>>((const __half2*)pvh, N / NSB, ppart);
    reduce_affine_v<<<CH, 256>>>(ppart, gv, bv, pvab, invN);
    // vr = relu(bn(v)) fp16 — FULL N*CH extent (round-5 bug: used N*C/2)
    {
        const int n2 = N * CH / 2;   // number of half2 elements in v
        vrelu_kernel<<<n2 / 256, 256>>>(
            (const __half2*)pvh, pvab, (__half2*)pvr, n2);
    }
    // ksum from codebook
    ksum_kernel<<<MM * KK, 256>>>(cb, pksum);
    // q = gather-sum of P, with stats
    q_gather<<<N / 256, 256>>>(nbr, pP, pq, pqpart);
    q_finalize<<<1, NSB>>>(pqpart, gq, bq, pqab, invN);
    // routing weights
    choice_kernel<<<N / 256, 256>>>(nbr, pq, pqab, pksum, pchoice);
    // routed channelwise gather conv -> hi/lo fp16 planes
    routed_gather<<<N / RG_ROWS, 256, RG_SMEM>>>(
        (const __half2*)pvr, nbr, pchoice, cb,
        (__half2*)po1h, (__half2*)po1l);
    // y = out1 @ Wout (pipelined fp16 split GEMM, fp32 out)
    hgemm16<256, false><<<dim3(N / 128, 1), 256, HG_SMEM>>>(
        po1h, po1l, pWoh, pWol, py, C);
    // y BN stats -> affine
    colstats_f32<<<NSB, 256>>>(py, (size_t)N * C / NSB, ppart);
    reduce_affine_y<<<C, 256>>>(ppart, go, bo, pyab, invN);
    // out = relu(bn(y)) + x
    final_kernel<<<(size_t)N * C / 256, 256>>>(py, x, pyab, out);
}